// round 8
// baseline (speedup 1.0000x reference)
#include <cuda_runtime.h>
#include <math.h>

#define NP 10000
#define NG 1000
#define NC 80
#define PMAX 2500
#define JT 20          // gts per block tile in cost_iou_kernel

// ---- persistent device scratch ----
__device__ float  g_cost[(size_t)NG * NP];   // column-major: [j][i]
__device__ float  g_iou [(size_t)NG * NP];   // column-major: [j][i]
__device__ float  g_cls [(size_t)NC * NP];   // transposed cls cost table
__device__ float4 g_pn  [NP];
__device__ float  g_vadd[NP];
__device__ int    g_rowcnt[NP];
__device__ int    g_minGt [NP];              // min matched gt (non-prior rows)
__device__ int    g_priorFlag[NP];
__device__ int    g_colcnt[NG];
__device__ int    g_cand[NG * 5];            // per-gt sorted 5 lowest-cost preds
__device__ int    g_dk[NG];
__device__ int    g_priorCount;
__device__ int    g_priorList[PMAX];
__device__ int    g_priorCur [PMAX];
__device__ float  g_priorCost[(size_t)PMAX * NG];

__device__ __forceinline__ float cls_cost_f(float x) {
    float p   = (x >= 0.f) ? (1.f / (1.f + expf(-x))) : (expf(x) / (1.f + expf(x)));
    float omp = 1.f - p;
    float pos = -logf(p + 1e-12f) * 0.25f * (omp * omp);
    float neg = -log1pf(-(p - 1e-12f)) * 0.75f * (p * p);
    return (pos - neg) * 2.0f;
}

__device__ __forceinline__ bool cost_less(float av, int ai, float bv, int bi) {
    return (av < bv) || (av == bv && ai < bi);
}

__global__ void init_kernel() {
    int t = blockIdx.x * blockDim.x + threadIdx.x;
    if (t < NP) { g_rowcnt[t] = 0; g_priorFlag[t] = 0; g_minGt[t] = 0x7fffffff; }
    if (t < NG) g_colcnt[t] = 0;
    if (t == 0) g_priorCount = 0;
}

// per-pred: cls table row (transposed), normalized box, validity
__global__ void prep_kernel(const float* __restrict__ logits,
                            const float* __restrict__ pb, const float* __restrict__ gb,
                            const int* __restrict__ p_h, const int* __restrict__ p_w) {
    __shared__ float4 sg[NG];
    for (int j = threadIdx.x; j < NG; j += blockDim.x)
        sg[j] = reinterpret_cast<const float4*>(gb)[j];
    __syncthreads();
    int i = blockIdx.x * blockDim.x + threadIdx.x;
    if (i >= NP) return;

    const float4* row = reinterpret_cast<const float4*>(logits + (size_t)i * NC);
    #pragma unroll
    for (int q = 0; q < NC / 4; q++) {
        float4 v = row[q];
        g_cls[(q * 4 + 0) * NP + i] = cls_cost_f(v.x);
        g_cls[(q * 4 + 1) * NP + i] = cls_cost_f(v.y);
        g_cls[(q * 4 + 2) * NP + i] = cls_cost_f(v.z);
        g_cls[(q * 4 + 3) * NP + i] = cls_cost_f(v.w);
    }

    float fw = (float)(*p_w), fh = (float)(*p_h);
    float4 p = reinterpret_cast<const float4*>(pb)[i];
    float4 pn;
    pn.x = p.x / fw; pn.y = p.y / fh; pn.z = p.z / fw; pn.w = p.w / fh;
    g_pn[i] = pn;
    float pcx = (p.x + p.z) * 0.5f, pcy = (p.y + p.w) * 0.5f;
    int v = 0;
    for (int j = 0; j < NG; j++) {
        float4 g = sg[j];
        bool ib = (pcx > g.x) && (pcx < g.z) && (pcy > g.y) && (pcy < g.w);
        float gcx = (g.x + g.z) * 0.5f, gcy = (g.y + g.w) * 0.5f;
        float gw = g.z - g.x, gh = g.w - g.y;
        bool ic = (pcx > gcx - 2.5f * gw) && (pcx < gcx + 2.5f * gw) &&
                  (pcy > gcy - 2.5f * gh) && (pcy < gcy + 2.5f * gh);
        if (ib || ic) { v = 1; break; }
    }
    g_vadd[i] = v ? 0.0f : 10000.0f;
}

// Pure elementwise: cost + iou matrices. blockIdx.x -> i-tile, blockIdx.y -> j-tile.
__global__ void __launch_bounds__(256, 4)
cost_iou_kernel(const float* __restrict__ pb, const float* __restrict__ gb,
                const int* __restrict__ labels,
                const int* __restrict__ p_h, const int* __restrict__ p_w) {
    __shared__ float s_g[JT][12];
    __shared__ int   s_lab[JT];
    int j0 = blockIdx.y * JT;
    if (threadIdx.x < JT) {
        int j = j0 + threadIdx.x;
        float fw = (float)(*p_w), fh = (float)(*p_h);
        float4 g = reinterpret_cast<const float4*>(gb)[j];
        float gw = g.z - g.x, gh = g.w - g.y;
        s_g[threadIdx.x][0]  = g.x;
        s_g[threadIdx.x][1]  = g.y;
        s_g[threadIdx.x][2]  = g.z;
        s_g[threadIdx.x][3]  = g.w;
        s_g[threadIdx.x][4]  = gw * gh;                // area
        s_g[threadIdx.x][5]  = g.x / fw;               // n0
        s_g[threadIdx.x][6]  = g.y / fh;               // n1
        s_g[threadIdx.x][7]  = g.z / fw;               // n2
        s_g[threadIdx.x][8]  = g.w / fh;               // n3
        s_g[threadIdx.x][9]  = 0.f;
        s_g[threadIdx.x][10] = 0.f;
        s_g[threadIdx.x][11] = 0.f;
        s_lab[threadIdx.x] = labels[j];
    }
    __syncthreads();
    int i = blockIdx.x * 256 + threadIdx.x;
    if (i >= NP) return;

    float4 p  = reinterpret_cast<const float4*>(pb)[i];
    float4 pn = g_pn[i];
    float va  = g_vadd[i];
    float ap  = (p.z - p.x) * (p.w - p.y);
    float pcx = (p.x + p.z) * 0.5f, pcy = (p.y + p.w) * 0.5f;

    for (int t = 0; t < JT; t++) {
        int j = j0 + t;
        float gx1 = s_g[t][0], gy1 = s_g[t][1], gx2 = s_g[t][2], gy2 = s_g[t][3];
        float ag  = s_g[t][4];
        float n0 = s_g[t][5], n1 = s_g[t][6], n2 = s_g[t][7], n3 = s_g[t][8];
        float gcx = (gx1 + gx2) * 0.5f, gcy = (gy1 + gy2) * 0.5f;
        float gw = gx2 - gx1, gh = gy2 - gy1;

        float ltx = fmaxf(p.x, gx1), lty = fmaxf(p.y, gy1);
        float rbx = fminf(p.z, gx2), rby = fminf(p.w, gy2);
        float iw = fmaxf(rbx - ltx, 0.f), ih = fmaxf(rby - lty, 0.f);
        float inter = iw * ih;
        float uni = ap + ag - inter;
        float iou = inter / fmaxf(uni, 1e-12f);
        float ex = fmaxf(fmaxf(p.z, gx2) - fminf(p.x, gx1), 0.f);
        float ey = fmaxf(fmaxf(p.w, gy2) - fminf(p.y, gy1), 0.f);
        float enc = ex * ey;
        float giou = iou - (enc - uni) / fmaxf(enc, 1e-12f);
        float l1 = fabsf(pn.x - n0) + fabsf(pn.y - n1) +
                   fabsf(pn.z - n2) + fabsf(pn.w - n3);
        float cost = g_cls[(size_t)s_lab[t] * NP + i] + l1 * 5.0f + (-giou * 2.0f);
        bool ib = (pcx > gx1) && (pcx < gx2) && (pcy > gy1) && (pcy < gy2);
        bool ic = (pcx > gcx - 2.5f * gw) && (pcx < gcx + 2.5f * gw) &&
                  (pcy > gcy - 2.5f * gh) && (pcy < gcy + 2.5f * gh);
        cost = cost + ((ib && ic) ? 0.0f : 100.0f);
        cost = cost + va;
        g_cost[(size_t)j * NP + i] = cost;
        g_iou [(size_t)j * NP + i] = iou;
    }
}

__device__ __forceinline__ void merge_lists(float* aio, float* acv, int* aci,
                                            const float* bio, const float* bcv, const int* bci) {
    float rio[5];
    { int ia = 0, ib = 0;
      #pragma unroll
      for (int q = 0; q < 5; q++) rio[q] = (aio[ia] >= bio[ib]) ? aio[ia++] : bio[ib++];
    }
    float rcv[5]; int rci[5];
    { int ia = 0, ib = 0;
      #pragma unroll
      for (int q = 0; q < 5; q++) {
          if (cost_less(acv[ia], aci[ia], bcv[ib], bci[ib])) { rcv[q] = acv[ia]; rci[q] = aci[ia]; ia++; }
          else                                               { rcv[q] = bcv[ib]; rci[q] = bci[ib]; ib++; }
      }
    }
    #pragma unroll
    for (int q = 0; q < 5; q++) { aio[q] = rio[q]; acv[q] = rcv[q]; aci[q] = rci[q]; }
}

// block per gt: top-5 ious (dynamic_k) + 5 lowest (cost,idx); initial assignments.
__global__ void __launch_bounds__(256, 4) reduce_kernel() {
    int j = blockIdx.x;
    __shared__ float s_io[256 * 5];
    __shared__ float s_cv[256 * 5];
    __shared__ int   s_ci[256 * 5];
    const float4* c4 = reinterpret_cast<const float4*>(g_cost + (size_t)j * NP);
    const float4* o4 = reinterpret_cast<const float4*>(g_iou  + (size_t)j * NP);

    float i0 = -3.4e38f, i1 = -3.4e38f, i2 = -3.4e38f, i3 = -3.4e38f, i4 = -3.4e38f;
    float c0 = 3.4e38f, c1 = 3.4e38f, c2 = 3.4e38f, c3 = 3.4e38f, c4v = 3.4e38f;
    int   x0 = 0x7fffffff, x1 = 0x7fffffff, x2 = 0x7fffffff, x3 = 0x7fffffff, x4 = 0x7fffffff;

#define INS_IOU(v) do { float _v = (v);                                              \
    if (_v > i4) { i4 = _v;                                                          \
        if (i4 > i3) { float _t = i3; i3 = i4; i4 = _t;                              \
            if (i3 > i2) { _t = i2; i2 = i3; i3 = _t;                                \
                if (i2 > i1) { _t = i1; i1 = i2; i2 = _t;                            \
                    if (i1 > i0) { _t = i0; i0 = i1; i1 = _t; } } } } } } while (0)

#define INS_COST(v, idx) do { float _v = (v); int _i = (idx);                        \
    if (cost_less(_v, _i, c4v, x4)) { c4v = _v; x4 = _i;                             \
        if (cost_less(c4v, x4, c3, x3)) { float _t = c3; c3 = c4v; c4v = _t; int _u = x3; x3 = x4; x4 = _u; \
            if (cost_less(c3, x3, c2, x2)) { _t = c2; c2 = c3; c3 = _t; _u = x2; x2 = x3; x3 = _u; \
                if (cost_less(c2, x2, c1, x1)) { _t = c1; c1 = c2; c2 = _t; _u = x1; x1 = x2; x2 = _u; \
                    if (cost_less(c1, x1, c0, x0)) { _t = c0; c0 = c1; c1 = _t; _u = x0; x0 = x1; x1 = _u; } } } } } } while (0)

    for (int c = threadIdx.x; c < NP / 4; c += 256) {
        float4 cv = c4[c];
        float4 ov = o4[c];
        int b = c * 4;
        INS_IOU(ov.x); INS_IOU(ov.y); INS_IOU(ov.z); INS_IOU(ov.w);
        INS_COST(cv.x, b); INS_COST(cv.y, b + 1); INS_COST(cv.z, b + 2); INS_COST(cv.w, b + 3);
    }
#undef INS_IOU
#undef INS_COST

    int t = threadIdx.x;
    s_io[t*5+0]=i0; s_io[t*5+1]=i1; s_io[t*5+2]=i2; s_io[t*5+3]=i3; s_io[t*5+4]=i4;
    s_cv[t*5+0]=c0; s_cv[t*5+1]=c1; s_cv[t*5+2]=c2; s_cv[t*5+3]=c3; s_cv[t*5+4]=c4v;
    s_ci[t*5+0]=x0; s_ci[t*5+1]=x1; s_ci[t*5+2]=x2; s_ci[t*5+3]=x3; s_ci[t*5+4]=x4;
    __syncthreads();
    for (int stride = 128; stride > 0; stride >>= 1) {
        if (t < stride)
            merge_lists(&s_io[t*5], &s_cv[t*5], &s_ci[t*5],
                        &s_io[(t+stride)*5], &s_cv[(t+stride)*5], &s_ci[(t+stride)*5]);
        __syncthreads();
    }
    if (t == 0) {
        float s = 0.f;
        for (int q = 0; q < 5; q++) s += s_io[q];
        int dk = (int)s;
        if (dk < 1) dk = 1;
        if (dk > 5) dk = 5;
        g_dk[j] = dk;
        for (int q = 0; q < 5; q++) g_cand[j * 5 + q] = s_ci[q];
        for (int q = 0; q < dk; q++) {
            int r = s_ci[q];
            atomicMin(&g_minGt[r], j);
            atomicAdd(&g_rowcnt[r], 1);
        }
    }
}

// over-assigned rows -> one_hot(cmin); record as prior rows, gather row costs.
__global__ void fix_kernel() {
    int i = blockIdx.x * blockDim.x + threadIdx.x;
    if (i >= NP) return;
    if (g_rowcnt[i] > 1) {
        int p = atomicAdd(&g_priorCount, 1);
        if (p >= PMAX) return;
        float bv = 3.4e38f; int bj = 0;
        float* dst = g_priorCost + (size_t)p * NG;
        for (int j = 0; j < NG; j++) {
            float v = g_cost[(size_t)j * NP + i];
            dst[j] = v;
            if (v < bv) { bv = v; bj = j; }
        }
        g_priorFlag[i] = 1;
        g_priorList[p] = i;
        g_priorCur[p]  = bj;
        g_rowcnt[i] = 1;
    }
}

// Device-side while-loop + output write (single block, 1024 threads).
__global__ void loop_kernel(float* __restrict__ out) {
    __shared__ unsigned s_mb[(NP + 31) / 32];
    __shared__ short s_list[NG], s_sel[NG], s_fb[NG];
    __shared__ short s_pbj[PMAX];
    __shared__ int s_nA, s_nFb, s_conflict;
    int tid = threadIdx.x, wid = tid >> 5, lane = tid & 31;
    int P = g_priorCount;
    if (P > PMAX) P = PMAX;

    // colcnt: surviving initial assignments + prior rows' chosen columns
    for (int j = tid; j < NG; j += 1024) {
        int dk = g_dk[j], c = 0;
        for (int q = 0; q < dk; q++) {
            int r = g_cand[j * 5 + q];
            if (!g_priorFlag[r]) c++;
        }
        g_colcnt[j] = c;
    }
    __syncthreads();
    for (int p = tid; p < P; p += 1024) atomicAdd(&g_colcnt[g_priorCur[p]], 1);

    if (tid == 0) s_conflict = 0;
    for (int w = tid; w < (NP + 31) / 32; w += 1024) s_mb[w] = 0u;
    __syncthreads();
    for (int i = tid; i < NP; i += 1024)
        if (g_rowcnt[i] > 0) atomicOr(&s_mb[i >> 5], 1u << (i & 31));
    __syncthreads();

    for (int iter = 0; iter < 4096; iter++) {
        if (tid == 0) { s_nA = 0; s_nFb = 0; }
        __syncthreads();
        for (int gg = tid; gg < NG; gg += 1024)
            if (g_colcnt[gg] == 0) { int u = atomicAdd(&s_nA, 1); s_list[u] = (short)gg; }
        __syncthreads();
        int nA = s_nA;
        if (nA == 0) break;

        // prior rows: exact sequential +100000 accumulation and row argmin
        for (int p = wid; p < P; p += 32) {
            float* row = g_priorCost + (size_t)p * NG;
            float bv = 3.4e38f; int bj = 0x7fffffff;
            for (int jj = lane; jj < NG; jj += 32) {
                float v = row[jj] + 100000.0f;
                row[jj] = v;
                if (v < bv || (v == bv && jj < bj)) { bv = v; bj = jj; }
            }
            #pragma unroll
            for (int off = 16; off; off >>= 1) {
                float ov = __shfl_down_sync(0xffffffffu, bv, off);
                int   oj = __shfl_down_sync(0xffffffffu, bj, off);
                if (ov < bv || (ov == bv && oj < bj)) { bv = ov; bj = oj; }
            }
            if (lane == 0) s_pbj[p] = (short)bj;
        }

        // candidate walk: first unmatched among the 5 globally smallest
        for (int u = tid; u < nA; u += 1024) {
            int gg = s_list[u];
            int chosen = -1;
            #pragma unroll
            for (int q = 0; q < 5; q++) {
                int r = g_cand[gg * 5 + q];
                if (chosen < 0 && !((s_mb[r >> 5] >> (r & 31)) & 1u)) chosen = r;
            }
            if (chosen < 0) { int f = atomicAdd(&s_nFb, 1); s_fb[f] = (short)u; }
            s_sel[u] = (short)chosen;
        }
        __syncthreads();

        // fallback: full column scan over unmatched rows
        int nFb = s_nFb;
        for (int f = wid; f < nFb; f += 32) {
            int u = s_fb[f]; int gg = s_list[u];
            const float* col = g_cost + (size_t)gg * NP;
            float bv = 3.4e38f; int bi = 0x7fffffff;
            for (int i = lane; i < NP; i += 32) {
                if (!((s_mb[i >> 5] >> (i & 31)) & 1u)) {
                    float v = col[i];
                    if (v < bv || (v == bv && i < bi)) { bv = v; bi = i; }
                }
            }
            #pragma unroll
            for (int off = 16; off; off >>= 1) {
                float ov = __shfl_down_sync(0xffffffffu, bv, off);
                int   oi = __shfl_down_sync(0xffffffffu, bi, off);
                if (ov < bv || (ov == bv && oi < bi)) { bv = ov; bi = oi; }
            }
            if (lane == 0) s_sel[u] = (short)bi;
        }
        __syncthreads();

        // apply
        for (int u = tid; u < nA; u += 1024) {
            int r = (int)s_sel[u];
            if (r < 0) continue;
            int gg = s_list[u];
            atomicMin(&g_minGt[r], gg);
            int old = atomicAdd(&g_rowcnt[r], 1);
            if (old >= 1) atomicAdd(&s_conflict, 1);
            g_colcnt[gg] = 1;
        }
        __syncthreads();
        for (int u = tid; u < nA; u += 1024) {
            int r = (int)s_sel[u];
            if (r >= 0) atomicOr(&s_mb[r >> 5], 1u << (r & 31));
        }
        __syncthreads();

        // m_fix for prior rows (cumulative conflict flag, like reference)
        if (s_conflict > 0) {
            for (int p = tid; p < P; p += 1024) {
                int bj = (int)s_pbj[p];
                int cur = g_priorCur[p];
                if (bj != cur) {
                    atomicSub(&g_colcnt[cur], 1);
                    atomicAdd(&g_colcnt[bj], 1);
                    g_priorCur[p] = bj;
                }
            }
        }
        __syncthreads();
    }

    // outputs
    for (int i = tid; i < NP; i += 1024) {
        int fg = g_rowcnt[i] > 0;
        out[i] = fg ? 1.0f : 0.0f;
        int mg = 0;
        if (fg) { int m = g_minGt[i]; if (m != 0x7fffffff) mg = m; }
        out[NP + i] = (float)mg;
    }
    __syncthreads();
    for (int p = tid; p < P; p += 1024)
        out[NP + g_priorList[p]] = (float)g_priorCur[p];
}

extern "C" void kernel_launch(void* const* d_in, const int* in_sizes, int n_in,
                              void* d_out, int out_size) {
    const float* logits = (const float*)d_in[0];
    const float* pb     = (const float*)d_in[1];
    const float* gb     = (const float*)d_in[2];
    const int*   labels = (const int*)  d_in[3];
    const int*   p_h    = (const int*)  d_in[4];
    const int*   p_w    = (const int*)  d_in[5];

    init_kernel<<<(NP + 255) / 256, 256>>>();
    prep_kernel<<<(NP + 255) / 256, 256>>>(logits, pb, gb, p_h, p_w);
    dim3 gA((NP + 255) / 256, NG / JT);
    cost_iou_kernel<<<gA, 256>>>(pb, gb, labels, p_h, p_w);
    reduce_kernel<<<NG, 256>>>();
    fix_kernel<<<(NP + 255) / 256, 256>>>();
    loop_kernel<<<1, 1024>>>((float*)d_out);
}

// round 9
// speedup vs baseline: 2.0756x; 2.0756x over previous
#include <cuda_runtime.h>
#include <math.h>

#define NP 10000
#define NG 1000
#define NC 80
#define PMAX 2500

// ---- persistent device scratch ----
__device__ float  g_cost[(size_t)NG * NP];   // column-major: [j][i]
__device__ float  g_cls [(size_t)NC * NP];   // transposed cls cost table
__device__ float4 g_pn  [NP];
__device__ float  g_vadd[NP];
__device__ int    g_rowcnt[NP];
__device__ int    g_minGt [NP];
__device__ int    g_priorFlag[NP];
__device__ int    g_colcnt[NG];
__device__ int    g_cand[NG * 5];
__device__ int    g_dk[NG];
__device__ int    g_priorCount;
__device__ int    g_priorList[PMAX];
__device__ int    g_priorCur [PMAX];
__device__ float  g_priorCost[(size_t)PMAX * NG];

__device__ __forceinline__ float cls_cost_f(float x) {
    float p   = (x >= 0.f) ? (1.f / (1.f + expf(-x))) : (expf(x) / (1.f + expf(x)));
    float omp = 1.f - p;
    float pos = -logf(p + 1e-12f) * 0.25f * (omp * omp);
    float neg = -log1pf(-(p - 1e-12f)) * 0.75f * (p * p);
    return (pos - neg) * 2.0f;
}

__device__ __forceinline__ bool cost_less(float av, int ai, float bv, int bi) {
    return (av < bv) || (av == bv && ai < bi);
}

__global__ void init_kernel() {
    int t = blockIdx.x * blockDim.x + threadIdx.x;
    if (t < NP) { g_rowcnt[t] = 0; g_priorFlag[t] = 0; g_minGt[t] = 0x7fffffff; }
    if (t < NG) g_colcnt[t] = 0;
    if (t == 0) g_priorCount = 0;
}

// per-pred: cls table row (transposed), normalized box, validity
__global__ void prep_kernel(const float* __restrict__ logits,
                            const float* __restrict__ pb, const float* __restrict__ gb,
                            const int* __restrict__ p_h, const int* __restrict__ p_w) {
    __shared__ float4 sg[NG];
    for (int j = threadIdx.x; j < NG; j += blockDim.x)
        sg[j] = reinterpret_cast<const float4*>(gb)[j];
    __syncthreads();
    int i = blockIdx.x * blockDim.x + threadIdx.x;
    if (i >= NP) return;

    const float4* row = reinterpret_cast<const float4*>(logits + (size_t)i * NC);
    #pragma unroll
    for (int q = 0; q < NC / 4; q++) {
        float4 v = row[q];
        g_cls[(q * 4 + 0) * NP + i] = cls_cost_f(v.x);
        g_cls[(q * 4 + 1) * NP + i] = cls_cost_f(v.y);
        g_cls[(q * 4 + 2) * NP + i] = cls_cost_f(v.z);
        g_cls[(q * 4 + 3) * NP + i] = cls_cost_f(v.w);
    }

    float fw = (float)(*p_w), fh = (float)(*p_h);
    float4 p = reinterpret_cast<const float4*>(pb)[i];
    float4 pn;
    pn.x = p.x / fw; pn.y = p.y / fh; pn.z = p.z / fw; pn.w = p.w / fh;
    g_pn[i] = pn;
    float pcx = (p.x + p.z) * 0.5f, pcy = (p.y + p.w) * 0.5f;
    int v = 0;
    for (int j = 0; j < NG; j++) {
        float4 g = sg[j];
        bool ib = (pcx > g.x) && (pcx < g.z) && (pcy > g.y) && (pcy < g.w);
        float gcx = (g.x + g.z) * 0.5f, gcy = (g.y + g.w) * 0.5f;
        float gw = g.z - g.x, gh = g.w - g.y;
        bool ic = (pcx > gcx - 2.5f * gw) && (pcx < gcx + 2.5f * gw) &&
                  (pcy > gcy - 2.5f * gh) && (pcy < gcy + 2.5f * gh);
        if (ib || ic) { v = 1; break; }
    }
    g_vadd[i] = v ? 0.0f : 10000.0f;
}

__device__ __forceinline__ void merge_lists(float* aio, float* acv, int* aci,
                                            const float* bio, const float* bcv, const int* bci) {
    float rio[5];
    { int ia = 0, ib = 0;
      #pragma unroll
      for (int q = 0; q < 5; q++) rio[q] = (aio[ia] >= bio[ib]) ? aio[ia++] : bio[ib++];
    }
    float rcv[5]; int rci[5];
    { int ia = 0, ib = 0;
      #pragma unroll
      for (int q = 0; q < 5; q++) {
          if (cost_less(acv[ia], aci[ia], bcv[ib], bci[ib])) { rcv[q] = acv[ia]; rci[q] = aci[ia]; ia++; }
          else                                               { rcv[q] = bcv[ib]; rci[q] = bci[ib]; ib++; }
      }
    }
    #pragma unroll
    for (int q = 0; q < 5; q++) { aio[q] = rio[q]; acv[q] = rcv[q]; aci[q] = rci[q]; }
}

// FUSED: one block per gt. Cost column written once; scalar-register top-5
// ious (dynamic_k) + 5 lowest (cost,idx); initial assignments. No iou matrix.
__global__ void __launch_bounds__(256, 4)
pair_kernel(const float* __restrict__ pb, const float* __restrict__ gb,
            const int* __restrict__ labels,
            const int* __restrict__ p_h, const int* __restrict__ p_w) {
    int j = blockIdx.x;
    __shared__ float s_io[256 * 5];
    __shared__ float s_cv[256 * 5];
    __shared__ int   s_ci[256 * 5];

    float fw = (float)(*p_w), fh = (float)(*p_h);
    float4 g = reinterpret_cast<const float4*>(gb)[j];
    int lab = labels[j];
    float gx1 = g.x, gy1 = g.y, gx2 = g.z, gy2 = g.w;
    float ag  = (gx2 - gx1) * (gy2 - gy1);
    float gcx = (gx1 + gx2) * 0.5f, gcy = (gy1 + gy2) * 0.5f;
    float gw  = gx2 - gx1, gh = gy2 - gy1;
    float n0 = gx1 / fw, n1 = gy1 / fh, n2 = gx2 / fw, n3 = gy2 / fh;
    float lo_x = gcx - 2.5f * gw, hi_x = gcx + 2.5f * gw;
    float lo_y = gcy - 2.5f * gh, hi_y = gcy + 2.5f * gh;
    const float* __restrict__ clsCol  = g_cls + (size_t)lab * NP;
    float*       __restrict__ costCol = g_cost + (size_t)j * NP;

    // scalar top-5 state (no dynamic indexing -> no local-memory spills)
    float i0 = -3.4e38f, i1 = -3.4e38f, i2 = -3.4e38f, i3 = -3.4e38f, i4 = -3.4e38f;
    float c0 = 3.4e38f, c1 = 3.4e38f, c2 = 3.4e38f, c3 = 3.4e38f, c4v = 3.4e38f;
    int   x0 = 0x7fffffff, x1 = 0x7fffffff, x2 = 0x7fffffff, x3 = 0x7fffffff, x4 = 0x7fffffff;

#define INS_IOU(v) do { float _v = (v);                                              \
    if (_v > i4) { i4 = _v;                                                          \
        if (i4 > i3) { float _t = i3; i3 = i4; i4 = _t;                              \
            if (i3 > i2) { _t = i2; i2 = i3; i3 = _t;                                \
                if (i2 > i1) { _t = i1; i1 = i2; i2 = _t;                            \
                    if (i1 > i0) { _t = i0; i0 = i1; i1 = _t; } } } } } } while (0)

#define INS_COST(v, idx) do { float _v = (v); int _i = (idx);                        \
    if (cost_less(_v, _i, c4v, x4)) { c4v = _v; x4 = _i;                             \
        if (cost_less(c4v, x4, c3, x3)) { float _t = c3; c3 = c4v; c4v = _t; int _u = x3; x3 = x4; x4 = _u; \
            if (cost_less(c3, x3, c2, x2)) { _t = c2; c2 = c3; c3 = _t; _u = x2; x2 = x3; x3 = _u; \
                if (cost_less(c2, x2, c1, x1)) { _t = c1; c1 = c2; c2 = _t; _u = x1; x1 = x2; x2 = _u; \
                    if (cost_less(c1, x1, c0, x0)) { _t = c0; c0 = c1; c1 = _t; _u = x0; x0 = x1; x1 = _u; } } } } } } while (0)

    for (int i = threadIdx.x; i < NP; i += 256) {
        float4 p  = reinterpret_cast<const float4*>(pb)[i];
        float4 pn = g_pn[i];
        float ap  = (p.z - p.x) * (p.w - p.y);
        float ltx = fmaxf(p.x, gx1), lty = fmaxf(p.y, gy1);
        float rbx = fminf(p.z, gx2), rby = fminf(p.w, gy2);
        float iw = fmaxf(rbx - ltx, 0.f), ih = fmaxf(rby - lty, 0.f);
        float inter = iw * ih;
        float uni = ap + ag - inter;
        float iou = inter / fmaxf(uni, 1e-12f);
        float ex = fmaxf(fmaxf(p.z, gx2) - fminf(p.x, gx1), 0.f);
        float ey = fmaxf(fmaxf(p.w, gy2) - fminf(p.y, gy1), 0.f);
        float enc = ex * ey;
        float giou = iou - (enc - uni) / fmaxf(enc, 1e-12f);
        float l1 = fabsf(pn.x - n0) + fabsf(pn.y - n1) +
                   fabsf(pn.z - n2) + fabsf(pn.w - n3);
        float cost = clsCol[i] + l1 * 5.0f + (-giou * 2.0f);
        float pcx = (p.x + p.z) * 0.5f, pcy = (p.y + p.w) * 0.5f;
        bool ib = (pcx > gx1) && (pcx < gx2) && (pcy > gy1) && (pcy < gy2);
        bool ic = (pcx > lo_x) && (pcx < hi_x) && (pcy > lo_y) && (pcy < hi_y);
        cost = cost + ((ib && ic) ? 0.0f : 100.0f);
        cost = cost + g_vadd[i];
        costCol[i] = cost;

        INS_IOU(iou);
        INS_COST(cost, i);
    }
#undef INS_IOU
#undef INS_COST

    int t = threadIdx.x;
    s_io[t*5+0]=i0; s_io[t*5+1]=i1; s_io[t*5+2]=i2; s_io[t*5+3]=i3; s_io[t*5+4]=i4;
    s_cv[t*5+0]=c0; s_cv[t*5+1]=c1; s_cv[t*5+2]=c2; s_cv[t*5+3]=c3; s_cv[t*5+4]=c4v;
    s_ci[t*5+0]=x0; s_ci[t*5+1]=x1; s_ci[t*5+2]=x2; s_ci[t*5+3]=x3; s_ci[t*5+4]=x4;
    __syncthreads();
    for (int stride = 128; stride > 0; stride >>= 1) {
        if (t < stride)
            merge_lists(&s_io[t*5], &s_cv[t*5], &s_ci[t*5],
                        &s_io[(t+stride)*5], &s_cv[(t+stride)*5], &s_ci[(t+stride)*5]);
        __syncthreads();
    }
    if (t == 0) {
        float s = 0.f;
        for (int q = 0; q < 5; q++) s += s_io[q];
        int dk = (int)s;
        if (dk < 1) dk = 1;
        if (dk > 5) dk = 5;
        g_dk[j] = dk;
        for (int q = 0; q < 5; q++) g_cand[j * 5 + q] = s_ci[q];
        for (int q = 0; q < dk; q++) {
            int r = s_ci[q];
            atomicMin(&g_minGt[r], j);
            atomicAdd(&g_rowcnt[r], 1);
        }
    }
}

// over-assigned rows -> one_hot(cmin); record as prior rows (no gather here).
__global__ void fix_kernel() {
    int i = blockIdx.x * blockDim.x + threadIdx.x;
    if (i >= NP) return;
    if (g_rowcnt[i] > 1) {
        int p = atomicAdd(&g_priorCount, 1);
        if (p >= PMAX) return;
        float bv = 3.4e38f; int bj = 0;
        for (int j = 0; j < NG; j++) {
            float v = g_cost[(size_t)j * NP + i];
            if (v < bv) { bv = v; bj = j; }
        }
        g_priorFlag[i] = 1;
        g_priorList[p] = i;
        g_priorCur[p]  = bj;
        g_rowcnt[i] = 1;
    }
}

// Gather prior rows into compact row-major scratch (coalesced writes).
__global__ void gather_kernel() {
    int p = blockIdx.x;
    if (p >= g_priorCount || p >= PMAX) return;
    int i = g_priorList[p];
    for (int j = threadIdx.x; j < NG; j += blockDim.x)
        g_priorCost[(size_t)p * NG + j] = g_cost[(size_t)j * NP + i];
}

// Device-side while-loop + output write (single block, 1024 threads).
__global__ void loop_kernel(float* __restrict__ out) {
    __shared__ unsigned s_mb[(NP + 31) / 32];
    __shared__ short s_list[NG], s_sel[NG], s_fb[NG];
    __shared__ short s_pbj[PMAX];
    __shared__ int s_nA, s_nFb, s_conflict;
    int tid = threadIdx.x, wid = tid >> 5, lane = tid & 31;
    int P = g_priorCount;
    if (P > PMAX) P = PMAX;

    // colcnt: surviving initial assignments + prior rows' chosen columns
    for (int j = tid; j < NG; j += 1024) {
        int dk = g_dk[j], c = 0;
        for (int q = 0; q < dk; q++) {
            int r = g_cand[j * 5 + q];
            if (!g_priorFlag[r]) c++;
        }
        g_colcnt[j] = c;
    }
    __syncthreads();
    for (int p = tid; p < P; p += 1024) atomicAdd(&g_colcnt[g_priorCur[p]], 1);

    if (tid == 0) s_conflict = 0;
    for (int w = tid; w < (NP + 31) / 32; w += 1024) s_mb[w] = 0u;
    __syncthreads();
    for (int i = tid; i < NP; i += 1024)
        if (g_rowcnt[i] > 0) atomicOr(&s_mb[i >> 5], 1u << (i & 31));
    __syncthreads();

    for (int iter = 0; iter < 4096; iter++) {
        if (tid == 0) { s_nA = 0; s_nFb = 0; }
        __syncthreads();
        for (int gg = tid; gg < NG; gg += 1024)
            if (g_colcnt[gg] == 0) { int u = atomicAdd(&s_nA, 1); s_list[u] = (short)gg; }
        __syncthreads();
        int nA = s_nA;
        if (nA == 0) break;

        // prior rows: exact sequential +100000 accumulation and row argmin
        for (int p = wid; p < P; p += 32) {
            float* row = g_priorCost + (size_t)p * NG;
            float bv = 3.4e38f; int bj = 0x7fffffff;
            for (int jj = lane; jj < NG; jj += 32) {
                float v = row[jj] + 100000.0f;
                row[jj] = v;
                if (v < bv || (v == bv && jj < bj)) { bv = v; bj = jj; }
            }
            #pragma unroll
            for (int off = 16; off; off >>= 1) {
                float ov = __shfl_down_sync(0xffffffffu, bv, off);
                int   oj = __shfl_down_sync(0xffffffffu, bj, off);
                if (ov < bv || (ov == bv && oj < bj)) { bv = ov; bj = oj; }
            }
            if (lane == 0) s_pbj[p] = (short)bj;
        }

        // candidate walk: first unmatched among the 5 globally smallest
        for (int u = tid; u < nA; u += 1024) {
            int gg = s_list[u];
            int chosen = -1;
            #pragma unroll
            for (int q = 0; q < 5; q++) {
                int r = g_cand[gg * 5 + q];
                if (chosen < 0 && !((s_mb[r >> 5] >> (r & 31)) & 1u)) chosen = r;
            }
            if (chosen < 0) { int f = atomicAdd(&s_nFb, 1); s_fb[f] = (short)u; }
            s_sel[u] = (short)chosen;
        }
        __syncthreads();

        // fallback: full column scan over unmatched rows
        int nFb = s_nFb;
        for (int f = wid; f < nFb; f += 32) {
            int u = s_fb[f]; int gg = s_list[u];
            const float* col = g_cost + (size_t)gg * NP;
            float bv = 3.4e38f; int bi = 0x7fffffff;
            for (int i = lane; i < NP; i += 32) {
                if (!((s_mb[i >> 5] >> (i & 31)) & 1u)) {
                    float v = col[i];
                    if (v < bv || (v == bv && i < bi)) { bv = v; bi = i; }
                }
            }
            #pragma unroll
            for (int off = 16; off; off >>= 1) {
                float ov = __shfl_down_sync(0xffffffffu, bv, off);
                int   oi = __shfl_down_sync(0xffffffffu, bi, off);
                if (ov < bv || (ov == bv && oi < bi)) { bv = ov; bi = oi; }
            }
            if (lane == 0) s_sel[u] = (short)bi;
        }
        __syncthreads();

        // apply
        for (int u = tid; u < nA; u += 1024) {
            int r = (int)s_sel[u];
            if (r < 0) continue;
            int gg = s_list[u];
            atomicMin(&g_minGt[r], gg);
            int old = atomicAdd(&g_rowcnt[r], 1);
            if (old >= 1) atomicAdd(&s_conflict, 1);
            g_colcnt[gg] = 1;
        }
        __syncthreads();
        for (int u = tid; u < nA; u += 1024) {
            int r = (int)s_sel[u];
            if (r >= 0) atomicOr(&s_mb[r >> 5], 1u << (r & 31));
        }
        __syncthreads();

        // m_fix for prior rows (cumulative conflict flag, like reference)
        if (s_conflict > 0) {
            for (int p = tid; p < P; p += 1024) {
                int bj = (int)s_pbj[p];
                int cur = g_priorCur[p];
                if (bj != cur) {
                    atomicSub(&g_colcnt[cur], 1);
                    atomicAdd(&g_colcnt[bj], 1);
                    g_priorCur[p] = bj;
                }
            }
        }
        __syncthreads();
    }

    // outputs
    for (int i = tid; i < NP; i += 1024) {
        int fg = g_rowcnt[i] > 0;
        out[i] = fg ? 1.0f : 0.0f;
        int mg = 0;
        if (fg) { int m = g_minGt[i]; if (m != 0x7fffffff) mg = m; }
        out[NP + i] = (float)mg;
    }
    __syncthreads();
    for (int p = tid; p < P; p += 1024)
        out[NP + g_priorList[p]] = (float)g_priorCur[p];
}

extern "C" void kernel_launch(void* const* d_in, const int* in_sizes, int n_in,
                              void* d_out, int out_size) {
    const float* logits = (const float*)d_in[0];
    const float* pb     = (const float*)d_in[1];
    const float* gb     = (const float*)d_in[2];
    const int*   labels = (const int*)  d_in[3];
    const int*   p_h    = (const int*)  d_in[4];
    const int*   p_w    = (const int*)  d_in[5];

    init_kernel<<<(NP + 255) / 256, 256>>>();
    prep_kernel<<<(NP + 255) / 256, 256>>>(logits, pb, gb, p_h, p_w);
    pair_kernel<<<NG, 256>>>(pb, gb, labels, p_h, p_w);
    fix_kernel<<<(NP + 255) / 256, 256>>>();
    gather_kernel<<<PMAX, 128>>>();
    loop_kernel<<<1, 1024>>>((float*)d_out);
}

// round 10
// speedup vs baseline: 2.3667x; 1.1402x over previous
#include <cuda_runtime.h>
#include <math.h>

#define NP 10000
#define NG 1000
#define NC 80
#define PMAX 2500

// ---- persistent device scratch ----
__device__ float  g_cost[(size_t)NG * NP];   // column-major: [j][i]
__device__ float  g_cls [(size_t)NC * NP];   // transposed cls cost table
__device__ float4 g_pn  [NP];
__device__ float  g_vadd[NP];
__device__ int    g_rowcnt[NP];
__device__ int    g_minGt [NP];
__device__ int    g_priorFlag[NP];
__device__ int    g_colcnt[NG];
__device__ int    g_cand[NG * 5];
__device__ int    g_dk[NG];
__device__ int    g_priorCount;
__device__ int    g_priorList[PMAX];
__device__ int    g_priorCur [PMAX];
__device__ float  g_priorCost[(size_t)PMAX * NG];

__device__ __forceinline__ float cls_cost_f(float x) {
    float p   = (x >= 0.f) ? (1.f / (1.f + expf(-x))) : (expf(x) / (1.f + expf(x)));
    float omp = 1.f - p;
    float pos = -logf(p + 1e-12f) * 0.25f * (omp * omp);
    float neg = -log1pf(-(p - 1e-12f)) * 0.75f * (p * p);
    return (pos - neg) * 2.0f;
}

__device__ __forceinline__ bool cost_less(float av, int ai, float bv, int bi) {
    return (av < bv) || (av == bv && ai < bi);
}

__global__ void init_kernel() {
    int t = blockIdx.x * blockDim.x + threadIdx.x;
    if (t < NP) { g_rowcnt[t] = 0; g_priorFlag[t] = 0; g_minGt[t] = 0x7fffffff; }
    if (t < NG) g_colcnt[t] = 0;
    if (t == 0) g_priorCount = 0;
}

// per-pred: cls table row (transposed), normalized box, validity
__global__ void prep_kernel(const float* __restrict__ logits,
                            const float* __restrict__ pb, const float* __restrict__ gb,
                            const int* __restrict__ p_h, const int* __restrict__ p_w) {
    __shared__ float4 sg[NG];
    for (int j = threadIdx.x; j < NG; j += blockDim.x)
        sg[j] = reinterpret_cast<const float4*>(gb)[j];
    __syncthreads();
    int i = blockIdx.x * blockDim.x + threadIdx.x;
    if (i >= NP) return;

    const float4* row = reinterpret_cast<const float4*>(logits + (size_t)i * NC);
    #pragma unroll
    for (int q = 0; q < NC / 4; q++) {
        float4 v = row[q];
        g_cls[(q * 4 + 0) * NP + i] = cls_cost_f(v.x);
        g_cls[(q * 4 + 1) * NP + i] = cls_cost_f(v.y);
        g_cls[(q * 4 + 2) * NP + i] = cls_cost_f(v.z);
        g_cls[(q * 4 + 3) * NP + i] = cls_cost_f(v.w);
    }

    float fw = (float)(*p_w), fh = (float)(*p_h);
    float4 p = reinterpret_cast<const float4*>(pb)[i];
    float4 pn;
    pn.x = p.x / fw; pn.y = p.y / fh; pn.z = p.z / fw; pn.w = p.w / fh;
    g_pn[i] = pn;
    float pcx = (p.x + p.z) * 0.5f, pcy = (p.y + p.w) * 0.5f;
    int v = 0;
    for (int j = 0; j < NG; j++) {
        float4 g = sg[j];
        bool ib = (pcx > g.x) && (pcx < g.z) && (pcy > g.y) && (pcy < g.w);
        float gcx = (g.x + g.z) * 0.5f, gcy = (g.y + g.w) * 0.5f;
        float gw = g.z - g.x, gh = g.w - g.y;
        bool ic = (pcx > gcx - 2.5f * gw) && (pcx < gcx + 2.5f * gw) &&
                  (pcy > gcy - 2.5f * gh) && (pcy < gcy + 2.5f * gh);
        if (ib || ic) { v = 1; break; }
    }
    g_vadd[i] = v ? 0.0f : 10000.0f;
}

__device__ __forceinline__ void merge_lists(float* aio, float* acv, int* aci,
                                            const float* bio, const float* bcv, const int* bci) {
    float rio[5];
    { int ia = 0, ib = 0;
      #pragma unroll
      for (int q = 0; q < 5; q++) rio[q] = (aio[ia] >= bio[ib]) ? aio[ia++] : bio[ib++];
    }
    float rcv[5]; int rci[5];
    { int ia = 0, ib = 0;
      #pragma unroll
      for (int q = 0; q < 5; q++) {
          if (cost_less(acv[ia], aci[ia], bcv[ib], bci[ib])) { rcv[q] = acv[ia]; rci[q] = aci[ia]; ia++; }
          else                                               { rcv[q] = bcv[ib]; rci[q] = bci[ib]; ib++; }
      }
    }
    #pragma unroll
    for (int q = 0; q < 5; q++) { aio[q] = rio[q]; acv[q] = rcv[q]; aci[q] = rci[q]; }
}

// FUSED: one block per gt. Cost column written once; scalar-register top-5
// ious (dynamic_k) + 5 lowest (cost,idx); initial assignments.
__global__ void __launch_bounds__(256, 4)
pair_kernel(const float* __restrict__ pb, const float* __restrict__ gb,
            const int* __restrict__ labels,
            const int* __restrict__ p_h, const int* __restrict__ p_w) {
    int j = blockIdx.x;
    __shared__ float s_io[256 * 5];
    __shared__ float s_cv[256 * 5];
    __shared__ int   s_ci[256 * 5];

    float fw = (float)(*p_w), fh = (float)(*p_h);
    float4 g = reinterpret_cast<const float4*>(gb)[j];
    int lab = labels[j];
    float gx1 = g.x, gy1 = g.y, gx2 = g.z, gy2 = g.w;
    float ag  = (gx2 - gx1) * (gy2 - gy1);
    float gcx = (gx1 + gx2) * 0.5f, gcy = (gy1 + gy2) * 0.5f;
    float gw  = gx2 - gx1, gh = gy2 - gy1;
    float n0 = gx1 / fw, n1 = gy1 / fh, n2 = gx2 / fw, n3 = gy2 / fh;
    float lo_x = gcx - 2.5f * gw, hi_x = gcx + 2.5f * gw;
    float lo_y = gcy - 2.5f * gh, hi_y = gcy + 2.5f * gh;
    const float* __restrict__ clsCol  = g_cls + (size_t)lab * NP;
    float*       __restrict__ costCol = g_cost + (size_t)j * NP;

    float i0 = -3.4e38f, i1 = -3.4e38f, i2 = -3.4e38f, i3 = -3.4e38f, i4 = -3.4e38f;
    float c0 = 3.4e38f, c1 = 3.4e38f, c2 = 3.4e38f, c3 = 3.4e38f, c4v = 3.4e38f;
    int   x0 = 0x7fffffff, x1 = 0x7fffffff, x2 = 0x7fffffff, x3 = 0x7fffffff, x4 = 0x7fffffff;

#define INS_IOU(v) do { float _v = (v);                                              \
    if (_v > i4) { i4 = _v;                                                          \
        if (i4 > i3) { float _t = i3; i3 = i4; i4 = _t;                              \
            if (i3 > i2) { _t = i2; i2 = i3; i3 = _t;                                \
                if (i2 > i1) { _t = i1; i1 = i2; i2 = _t;                            \
                    if (i1 > i0) { _t = i0; i0 = i1; i1 = _t; } } } } } } while (0)

#define INS_COST(v, idx) do { float _v = (v); int _i = (idx);                        \
    if (cost_less(_v, _i, c4v, x4)) { c4v = _v; x4 = _i;                             \
        if (cost_less(c4v, x4, c3, x3)) { float _t = c3; c3 = c4v; c4v = _t; int _u = x3; x3 = x4; x4 = _u; \
            if (cost_less(c3, x3, c2, x2)) { _t = c2; c2 = c3; c3 = _t; _u = x2; x2 = x3; x3 = _u; \
                if (cost_less(c2, x2, c1, x1)) { _t = c1; c1 = c2; c2 = _t; _u = x1; x1 = x2; x2 = _u; \
                    if (cost_less(c1, x1, c0, x0)) { _t = c0; c0 = c1; c1 = _t; _u = x0; x0 = x1; x1 = _u; } } } } } } while (0)

    for (int i = threadIdx.x; i < NP; i += 256) {
        float4 p  = reinterpret_cast<const float4*>(pb)[i];
        float4 pn = g_pn[i];
        float ap  = (p.z - p.x) * (p.w - p.y);
        float ltx = fmaxf(p.x, gx1), lty = fmaxf(p.y, gy1);
        float rbx = fminf(p.z, gx2), rby = fminf(p.w, gy2);
        float iw = fmaxf(rbx - ltx, 0.f), ih = fmaxf(rby - lty, 0.f);
        float inter = iw * ih;
        float uni = ap + ag - inter;
        float iou = inter / fmaxf(uni, 1e-12f);
        float ex = fmaxf(fmaxf(p.z, gx2) - fminf(p.x, gx1), 0.f);
        float ey = fmaxf(fmaxf(p.w, gy2) - fminf(p.y, gy1), 0.f);
        float enc = ex * ey;
        float giou = iou - (enc - uni) / fmaxf(enc, 1e-12f);
        float l1 = fabsf(pn.x - n0) + fabsf(pn.y - n1) +
                   fabsf(pn.z - n2) + fabsf(pn.w - n3);
        float cost = clsCol[i] + l1 * 5.0f + (-giou * 2.0f);
        float pcx = (p.x + p.z) * 0.5f, pcy = (p.y + p.w) * 0.5f;
        bool ib = (pcx > gx1) && (pcx < gx2) && (pcy > gy1) && (pcy < gy2);
        bool ic = (pcx > lo_x) && (pcx < hi_x) && (pcy > lo_y) && (pcy < hi_y);
        cost = cost + ((ib && ic) ? 0.0f : 100.0f);
        cost = cost + g_vadd[i];
        costCol[i] = cost;

        INS_IOU(iou);
        INS_COST(cost, i);
    }
#undef INS_IOU
#undef INS_COST

    int t = threadIdx.x;
    s_io[t*5+0]=i0; s_io[t*5+1]=i1; s_io[t*5+2]=i2; s_io[t*5+3]=i3; s_io[t*5+4]=i4;
    s_cv[t*5+0]=c0; s_cv[t*5+1]=c1; s_cv[t*5+2]=c2; s_cv[t*5+3]=c3; s_cv[t*5+4]=c4v;
    s_ci[t*5+0]=x0; s_ci[t*5+1]=x1; s_ci[t*5+2]=x2; s_ci[t*5+3]=x3; s_ci[t*5+4]=x4;
    __syncthreads();
    for (int stride = 128; stride > 0; stride >>= 1) {
        if (t < stride)
            merge_lists(&s_io[t*5], &s_cv[t*5], &s_ci[t*5],
                        &s_io[(t+stride)*5], &s_cv[(t+stride)*5], &s_ci[(t+stride)*5]);
        __syncthreads();
    }
    if (t == 0) {
        float s = 0.f;
        for (int q = 0; q < 5; q++) s += s_io[q];
        int dk = (int)s;
        if (dk < 1) dk = 1;
        if (dk > 5) dk = 5;
        g_dk[j] = dk;
        for (int q = 0; q < 5; q++) g_cand[j * 5 + q] = s_ci[q];
        for (int q = 0; q < dk; q++) {
            int r = s_ci[q];
            atomicMin(&g_minGt[r], j);
            atomicAdd(&g_rowcnt[r], 1);
        }
    }
}

// over-assigned rows: flag + append only (argmin moved to gather_kernel).
__global__ void fix_kernel() {
    int i = blockIdx.x * blockDim.x + threadIdx.x;
    if (i >= NP) return;
    if (g_rowcnt[i] > 1) {
        int p = atomicAdd(&g_priorCount, 1);
        if (p < PMAX) {
            g_priorFlag[i] = 1;
            g_priorList[p] = i;
        }
        g_rowcnt[i] = 1;
    }
}

// Gather prior rows into compact row-major scratch AND compute the row argmin
// (one_hot(cmin) column) in the same pass — same values, same lowest-index
// tie-break as the reference jnp.argmin.
__global__ void gather_kernel() {
    int p = blockIdx.x;
    if (p >= g_priorCount || p >= PMAX) return;
    int i = g_priorList[p];
    __shared__ float s_v[256];
    __shared__ int   s_j[256];
    float bv = 3.4e38f; int bj = 0x7fffffff;
    for (int j = threadIdx.x; j < NG; j += 256) {
        float v = g_cost[(size_t)j * NP + i];
        g_priorCost[(size_t)p * NG + j] = v;
        if (v < bv) { bv = v; bj = j; }   // ascending j per thread -> lowest j kept on ties
    }
    s_v[threadIdx.x] = bv; s_j[threadIdx.x] = bj;
    __syncthreads();
    for (int s = 128; s > 0; s >>= 1) {
        if (threadIdx.x < s) {
            float ov = s_v[threadIdx.x + s]; int oj = s_j[threadIdx.x + s];
            if (ov < s_v[threadIdx.x] || (ov == s_v[threadIdx.x] && oj < s_j[threadIdx.x])) {
                s_v[threadIdx.x] = ov; s_j[threadIdx.x] = oj;
            }
        }
        __syncthreads();
    }
    if (threadIdx.x == 0) g_priorCur[p] = s_j[0];
}

// Device-side while-loop + output write (single block, 1024 threads).
__global__ void loop_kernel(float* __restrict__ out) {
    __shared__ unsigned s_mb[(NP + 31) / 32];
    __shared__ short s_list[NG], s_sel[NG], s_fb[NG];
    __shared__ short s_pbj[PMAX];
    __shared__ int s_nA, s_nFb, s_conflict;
    int tid = threadIdx.x, wid = tid >> 5, lane = tid & 31;
    int P = g_priorCount;
    if (P > PMAX) P = PMAX;

    // colcnt: surviving initial assignments + prior rows' chosen columns
    for (int j = tid; j < NG; j += 1024) {
        int dk = g_dk[j], c = 0;
        for (int q = 0; q < dk; q++) {
            int r = g_cand[j * 5 + q];
            if (!g_priorFlag[r]) c++;
        }
        g_colcnt[j] = c;
    }
    __syncthreads();
    for (int p = tid; p < P; p += 1024) atomicAdd(&g_colcnt[g_priorCur[p]], 1);

    if (tid == 0) s_conflict = 0;
    for (int w = tid; w < (NP + 31) / 32; w += 1024) s_mb[w] = 0u;
    __syncthreads();
    for (int i = tid; i < NP; i += 1024)
        if (g_rowcnt[i] > 0) atomicOr(&s_mb[i >> 5], 1u << (i & 31));
    __syncthreads();

    for (int iter = 0; iter < 4096; iter++) {
        if (tid == 0) { s_nA = 0; s_nFb = 0; }
        __syncthreads();
        for (int gg = tid; gg < NG; gg += 1024)
            if (g_colcnt[gg] == 0) { int u = atomicAdd(&s_nA, 1); s_list[u] = (short)gg; }
        __syncthreads();
        int nA = s_nA;
        if (nA == 0) break;

        // prior rows: exact sequential +100000 accumulation and row argmin
        for (int p = wid; p < P; p += 32) {
            float* row = g_priorCost + (size_t)p * NG;
            float bv = 3.4e38f; int bj = 0x7fffffff;
            for (int jj = lane; jj < NG; jj += 32) {
                float v = row[jj] + 100000.0f;
                row[jj] = v;
                if (v < bv || (v == bv && jj < bj)) { bv = v; bj = jj; }
            }
            #pragma unroll
            for (int off = 16; off; off >>= 1) {
                float ov = __shfl_down_sync(0xffffffffu, bv, off);
                int   oj = __shfl_down_sync(0xffffffffu, bj, off);
                if (ov < bv || (ov == bv && oj < bj)) { bv = ov; bj = oj; }
            }
            if (lane == 0) s_pbj[p] = (short)bj;
        }

        // candidate walk: first unmatched among the 5 globally smallest
        for (int u = tid; u < nA; u += 1024) {
            int gg = s_list[u];
            int chosen = -1;
            #pragma unroll
            for (int q = 0; q < 5; q++) {
                int r = g_cand[gg * 5 + q];
                if (chosen < 0 && !((s_mb[r >> 5] >> (r & 31)) & 1u)) chosen = r;
            }
            if (chosen < 0) { int f = atomicAdd(&s_nFb, 1); s_fb[f] = (short)u; }
            s_sel[u] = (short)chosen;
        }
        __syncthreads();

        // fallback: full column scan over unmatched rows
        int nFb = s_nFb;
        for (int f = wid; f < nFb; f += 32) {
            int u = s_fb[f]; int gg = s_list[u];
            const float* col = g_cost + (size_t)gg * NP;
            float bv = 3.4e38f; int bi = 0x7fffffff;
            for (int i = lane; i < NP; i += 32) {
                if (!((s_mb[i >> 5] >> (i & 31)) & 1u)) {
                    float v = col[i];
                    if (v < bv || (v == bv && i < bi)) { bv = v; bi = i; }
                }
            }
            #pragma unroll
            for (int off = 16; off; off >>= 1) {
                float ov = __shfl_down_sync(0xffffffffu, bv, off);
                int   oi = __shfl_down_sync(0xffffffffu, bi, off);
                if (ov < bv || (ov == bv && oi < bi)) { bv = ov; bi = oi; }
            }
            if (lane == 0) s_sel[u] = (short)bi;
        }
        __syncthreads();

        // apply
        for (int u = tid; u < nA; u += 1024) {
            int r = (int)s_sel[u];
            if (r < 0) continue;
            int gg = s_list[u];
            atomicMin(&g_minGt[r], gg);
            int old = atomicAdd(&g_rowcnt[r], 1);
            if (old >= 1) atomicAdd(&s_conflict, 1);
            g_colcnt[gg] = 1;
        }
        __syncthreads();
        for (int u = tid; u < nA; u += 1024) {
            int r = (int)s_sel[u];
            if (r >= 0) atomicOr(&s_mb[r >> 5], 1u << (r & 31));
        }
        __syncthreads();

        // m_fix for prior rows (cumulative conflict flag, like reference)
        if (s_conflict > 0) {
            for (int p = tid; p < P; p += 1024) {
                int bj = (int)s_pbj[p];
                int cur = g_priorCur[p];
                if (bj != cur) {
                    atomicSub(&g_colcnt[cur], 1);
                    atomicAdd(&g_colcnt[bj], 1);
                    g_priorCur[p] = bj;
                }
            }
        }
        __syncthreads();
    }

    // outputs
    for (int i = tid; i < NP; i += 1024) {
        int fg = g_rowcnt[i] > 0;
        out[i] = fg ? 1.0f : 0.0f;
        int mg = 0;
        if (fg) { int m = g_minGt[i]; if (m != 0x7fffffff) mg = m; }
        out[NP + i] = (float)mg;
    }
    __syncthreads();
    for (int p = tid; p < P; p += 1024)
        out[NP + g_priorList[p]] = (float)g_priorCur[p];
}

extern "C" void kernel_launch(void* const* d_in, const int* in_sizes, int n_in,
                              void* d_out, int out_size) {
    const float* logits = (const float*)d_in[0];
    const float* pb     = (const float*)d_in[1];
    const float* gb     = (const float*)d_in[2];
    const int*   labels = (const int*)  d_in[3];
    const int*   p_h    = (const int*)  d_in[4];
    const int*   p_w    = (const int*)  d_in[5];

    init_kernel<<<(NP + 255) / 256, 256>>>();
    prep_kernel<<<(NP + 255) / 256, 256>>>(logits, pb, gb, p_h, p_w);
    pair_kernel<<<NG, 256>>>(pb, gb, labels, p_h, p_w);
    fix_kernel<<<(NP + 255) / 256, 256>>>();
    gather_kernel<<<PMAX, 256>>>();
    loop_kernel<<<1, 1024>>>((float*)d_out);
}

// round 11
// speedup vs baseline: 2.7889x; 1.1784x over previous
#include <cuda_runtime.h>
#include <math.h>

#define NP 10000
#define NG 1000
#define NC 80
#define PMAX 2500

// ---- persistent device scratch ----
__device__ float  g_cost[(size_t)NG * NP];   // column-major: [j][i]
__device__ float  g_cls [(size_t)NC * NP];   // transposed cls cost table
__device__ float4 g_pn  [NP];
__device__ float  g_vadd[NP];
__device__ int    g_rowcnt[NP];
__device__ int    g_minGt [NP];
__device__ int    g_priorFlag[NP];
__device__ int    g_colcnt[NG];
__device__ int    g_cand[NG * 5];
__device__ int    g_dk[NG];
__device__ int    g_priorCount;
__device__ int    g_priorList[PMAX];
__device__ int    g_priorCur [PMAX];
__device__ float  g_priorCost[(size_t)PMAX * NG];

__device__ __forceinline__ float cls_cost_f(float x) {
    float p   = (x >= 0.f) ? (1.f / (1.f + expf(-x))) : (expf(x) / (1.f + expf(x)));
    float omp = 1.f - p;
    float pos = -logf(p + 1e-12f) * 0.25f * (omp * omp);
    float neg = -log1pf(-(p - 1e-12f)) * 0.75f * (p * p);
    return (pos - neg) * 2.0f;
}

__device__ __forceinline__ bool cost_less(float av, int ai, float bv, int bi) {
    return (av < bv) || (av == bv && ai < bi);
}

__global__ void init_kernel() {
    int t = blockIdx.x * blockDim.x + threadIdx.x;
    if (t < NP) { g_rowcnt[t] = 0; g_priorFlag[t] = 0; g_minGt[t] = 0x7fffffff; }
    if (t < NG) g_colcnt[t] = 0;
    if (t == 0) g_priorCount = 0;
}

// per-pred: cls table row (transposed), normalized box, validity
__global__ void prep_kernel(const float* __restrict__ logits,
                            const float* __restrict__ pb, const float* __restrict__ gb,
                            const int* __restrict__ p_h, const int* __restrict__ p_w) {
    __shared__ float4 sg[NG];
    for (int j = threadIdx.x; j < NG; j += blockDim.x)
        sg[j] = reinterpret_cast<const float4*>(gb)[j];
    __syncthreads();
    int i = blockIdx.x * blockDim.x + threadIdx.x;
    if (i >= NP) return;

    const float4* row = reinterpret_cast<const float4*>(logits + (size_t)i * NC);
    #pragma unroll
    for (int q = 0; q < NC / 4; q++) {
        float4 v = row[q];
        g_cls[(q * 4 + 0) * NP + i] = cls_cost_f(v.x);
        g_cls[(q * 4 + 1) * NP + i] = cls_cost_f(v.y);
        g_cls[(q * 4 + 2) * NP + i] = cls_cost_f(v.z);
        g_cls[(q * 4 + 3) * NP + i] = cls_cost_f(v.w);
    }

    float fw = (float)(*p_w), fh = (float)(*p_h);
    float4 p = reinterpret_cast<const float4*>(pb)[i];
    float4 pn;
    pn.x = p.x / fw; pn.y = p.y / fh; pn.z = p.z / fw; pn.w = p.w / fh;
    g_pn[i] = pn;
    float pcx = (p.x + p.z) * 0.5f, pcy = (p.y + p.w) * 0.5f;
    int v = 0;
    for (int j = 0; j < NG; j++) {
        float4 g = sg[j];
        bool ib = (pcx > g.x) && (pcx < g.z) && (pcy > g.y) && (pcy < g.w);
        float gcx = (g.x + g.z) * 0.5f, gcy = (g.y + g.w) * 0.5f;
        float gw = g.z - g.x, gh = g.w - g.y;
        bool ic = (pcx > gcx - 2.5f * gw) && (pcx < gcx + 2.5f * gw) &&
                  (pcy > gcy - 2.5f * gh) && (pcy < gcy + 2.5f * gh);
        if (ib || ic) { v = 1; break; }
    }
    g_vadd[i] = v ? 0.0f : 10000.0f;
}

__device__ __forceinline__ void merge_lists(float* aio, float* acv, int* aci,
                                            const float* bio, const float* bcv, const int* bci) {
    float rio[5];
    { int ia = 0, ib = 0;
      #pragma unroll
      for (int q = 0; q < 5; q++) rio[q] = (aio[ia] >= bio[ib]) ? aio[ia++] : bio[ib++];
    }
    float rcv[5]; int rci[5];
    { int ia = 0, ib = 0;
      #pragma unroll
      for (int q = 0; q < 5; q++) {
          if (cost_less(acv[ia], aci[ia], bcv[ib], bci[ib])) { rcv[q] = acv[ia]; rci[q] = aci[ia]; ia++; }
          else                                               { rcv[q] = bcv[ib]; rci[q] = bci[ib]; ib++; }
      }
    }
    #pragma unroll
    for (int q = 0; q < 5; q++) { aio[q] = rio[q]; acv[q] = rcv[q]; aci[q] = rci[q]; }
}

// FUSED: one block per gt. Cost column written once; scalar-register top-5
// ious (dynamic_k) + 5 lowest (cost,idx); initial assignments.
__global__ void __launch_bounds__(256, 4)
pair_kernel(const float* __restrict__ pb, const float* __restrict__ gb,
            const int* __restrict__ labels,
            const int* __restrict__ p_h, const int* __restrict__ p_w) {
    int j = blockIdx.x;
    __shared__ float s_io[256 * 5];
    __shared__ float s_cv[256 * 5];
    __shared__ int   s_ci[256 * 5];

    float fw = (float)(*p_w), fh = (float)(*p_h);
    float4 g = reinterpret_cast<const float4*>(gb)[j];
    int lab = labels[j];
    float gx1 = g.x, gy1 = g.y, gx2 = g.z, gy2 = g.w;
    float ag  = (gx2 - gx1) * (gy2 - gy1);
    float gcx = (gx1 + gx2) * 0.5f, gcy = (gy1 + gy2) * 0.5f;
    float gw  = gx2 - gx1, gh = gy2 - gy1;
    float n0 = gx1 / fw, n1 = gy1 / fh, n2 = gx2 / fw, n3 = gy2 / fh;
    float lo_x = gcx - 2.5f * gw, hi_x = gcx + 2.5f * gw;
    float lo_y = gcy - 2.5f * gh, hi_y = gcy + 2.5f * gh;
    const float* __restrict__ clsCol  = g_cls + (size_t)lab * NP;
    float*       __restrict__ costCol = g_cost + (size_t)j * NP;

    float i0 = -3.4e38f, i1 = -3.4e38f, i2 = -3.4e38f, i3 = -3.4e38f, i4 = -3.4e38f;
    float c0 = 3.4e38f, c1 = 3.4e38f, c2 = 3.4e38f, c3 = 3.4e38f, c4v = 3.4e38f;
    int   x0 = 0x7fffffff, x1 = 0x7fffffff, x2 = 0x7fffffff, x3 = 0x7fffffff, x4 = 0x7fffffff;

#define INS_IOU(v) do { float _v = (v);                                              \
    if (_v > i4) { i4 = _v;                                                          \
        if (i4 > i3) { float _t = i3; i3 = i4; i4 = _t;                              \
            if (i3 > i2) { _t = i2; i2 = i3; i3 = _t;                                \
                if (i2 > i1) { _t = i1; i1 = i2; i2 = _t;                            \
                    if (i1 > i0) { _t = i0; i0 = i1; i1 = _t; } } } } } } while (0)

#define INS_COST(v, idx) do { float _v = (v); int _i = (idx);                        \
    if (cost_less(_v, _i, c4v, x4)) { c4v = _v; x4 = _i;                             \
        if (cost_less(c4v, x4, c3, x3)) { float _t = c3; c3 = c4v; c4v = _t; int _u = x3; x3 = x4; x4 = _u; \
            if (cost_less(c3, x3, c2, x2)) { _t = c2; c2 = c3; c3 = _t; _u = x2; x2 = x3; x3 = _u; \
                if (cost_less(c2, x2, c1, x1)) { _t = c1; c1 = c2; c2 = _t; _u = x1; x1 = x2; x2 = _u; \
                    if (cost_less(c1, x1, c0, x0)) { _t = c0; c0 = c1; c1 = _t; _u = x0; x0 = x1; x1 = _u; } } } } } } while (0)

    for (int i = threadIdx.x; i < NP; i += 256) {
        float4 p  = reinterpret_cast<const float4*>(pb)[i];
        float4 pn = g_pn[i];
        float ap  = (p.z - p.x) * (p.w - p.y);
        float ltx = fmaxf(p.x, gx1), lty = fmaxf(p.y, gy1);
        float rbx = fminf(p.z, gx2), rby = fminf(p.w, gy2);
        float iw = fmaxf(rbx - ltx, 0.f), ih = fmaxf(rby - lty, 0.f);
        float inter = iw * ih;
        float uni = ap + ag - inter;
        float iou = inter / fmaxf(uni, 1e-12f);
        float ex = fmaxf(fmaxf(p.z, gx2) - fminf(p.x, gx1), 0.f);
        float ey = fmaxf(fmaxf(p.w, gy2) - fminf(p.y, gy1), 0.f);
        float enc = ex * ey;
        float giou = iou - (enc - uni) / fmaxf(enc, 1e-12f);
        float l1 = fabsf(pn.x - n0) + fabsf(pn.y - n1) +
                   fabsf(pn.z - n2) + fabsf(pn.w - n3);
        float cost = clsCol[i] + l1 * 5.0f + (-giou * 2.0f);
        float pcx = (p.x + p.z) * 0.5f, pcy = (p.y + p.w) * 0.5f;
        bool ib = (pcx > gx1) && (pcx < gx2) && (pcy > gy1) && (pcy < gy2);
        bool ic = (pcx > lo_x) && (pcx < hi_x) && (pcy > lo_y) && (pcy < hi_y);
        cost = cost + ((ib && ic) ? 0.0f : 100.0f);
        cost = cost + g_vadd[i];
        costCol[i] = cost;

        INS_IOU(iou);
        INS_COST(cost, i);
    }
#undef INS_IOU
#undef INS_COST

    int t = threadIdx.x;
    s_io[t*5+0]=i0; s_io[t*5+1]=i1; s_io[t*5+2]=i2; s_io[t*5+3]=i3; s_io[t*5+4]=i4;
    s_cv[t*5+0]=c0; s_cv[t*5+1]=c1; s_cv[t*5+2]=c2; s_cv[t*5+3]=c3; s_cv[t*5+4]=c4v;
    s_ci[t*5+0]=x0; s_ci[t*5+1]=x1; s_ci[t*5+2]=x2; s_ci[t*5+3]=x3; s_ci[t*5+4]=x4;
    __syncthreads();
    for (int stride = 128; stride > 0; stride >>= 1) {
        if (t < stride)
            merge_lists(&s_io[t*5], &s_cv[t*5], &s_ci[t*5],
                        &s_io[(t+stride)*5], &s_cv[(t+stride)*5], &s_ci[(t+stride)*5]);
        __syncthreads();
    }
    if (t == 0) {
        float s = 0.f;
        for (int q = 0; q < 5; q++) s += s_io[q];
        int dk = (int)s;
        if (dk < 1) dk = 1;
        if (dk > 5) dk = 5;
        g_dk[j] = dk;
        for (int q = 0; q < 5; q++) g_cand[j * 5 + q] = s_ci[q];
        for (int q = 0; q < dk; q++) {
            int r = s_ci[q];
            atomicMin(&g_minGt[r], j);
            atomicAdd(&g_rowcnt[r], 1);
        }
    }
}

// over-assigned rows: flag + append only (argmin lives in gather_kernel).
__global__ void fix_kernel() {
    int i = blockIdx.x * blockDim.x + threadIdx.x;
    if (i >= NP) return;
    if (g_rowcnt[i] > 1) {
        int p = atomicAdd(&g_priorCount, 1);
        if (p < PMAX) {
            g_priorFlag[i] = 1;
            g_priorList[p] = i;
        }
        g_rowcnt[i] = 1;
    }
}

// Gather prior rows into compact row-major scratch AND compute the row argmin
// (one_hot(cmin) column) in the same pass.
__global__ void gather_kernel() {
    int p = blockIdx.x;
    if (p >= g_priorCount || p >= PMAX) return;
    int i = g_priorList[p];
    __shared__ float s_v[256];
    __shared__ int   s_j[256];
    float bv = 3.4e38f; int bj = 0x7fffffff;
    for (int j = threadIdx.x; j < NG; j += 256) {
        float v = g_cost[(size_t)j * NP + i];
        g_priorCost[(size_t)p * NG + j] = v;
        if (v < bv) { bv = v; bj = j; }   // ascending j per thread -> lowest j on ties
    }
    s_v[threadIdx.x] = bv; s_j[threadIdx.x] = bj;
    __syncthreads();
    for (int s = 128; s > 0; s >>= 1) {
        if (threadIdx.x < s) {
            float ov = s_v[threadIdx.x + s]; int oj = s_j[threadIdx.x + s];
            if (ov < s_v[threadIdx.x] || (ov == s_v[threadIdx.x] && oj < s_j[threadIdx.x])) {
                s_v[threadIdx.x] = ov; s_j[threadIdx.x] = oj;
            }
        }
        __syncthreads();
    }
    if (threadIdx.x == 0) g_priorCur[p] = s_j[0];
}

// Device-side while-loop + output write (single block, 1024 threads).
// Conflict latch (any(m.sum(1)>1)) is one-way: once a double-assigned row
// exists it persists, so m_fix runs every iteration thereafter. Before the
// first conflict, the prior-row penalty accumulation + argmin are never
// consumed, so we skip them and catch up EXACTLY (sequential +100000.0f adds)
// when the latch first fires.
__global__ void loop_kernel(float* __restrict__ out) {
    __shared__ unsigned s_mb[(NP + 31) / 32];
    __shared__ short s_list[NG], s_sel[NG], s_fb[NG];
    __shared__ short s_pbj[PMAX];
    __shared__ int s_nA, s_nFb, s_newc;
    int tid = threadIdx.x, wid = tid >> 5, lane = tid & 31;
    int P = g_priorCount;
    if (P > PMAX) P = PMAX;

    // colcnt: surviving initial assignments + prior rows' chosen columns
    for (int j = tid; j < NG; j += 1024) {
        int dk = g_dk[j], c = 0;
        for (int q = 0; q < dk; q++) {
            int r = g_cand[j * 5 + q];
            if (!g_priorFlag[r]) c++;
        }
        g_colcnt[j] = c;
    }
    __syncthreads();
    for (int p = tid; p < P; p += 1024) atomicAdd(&g_colcnt[g_priorCur[p]], 1);

    for (int w = tid; w < (NP + 31) / 32; w += 1024) s_mb[w] = 0u;
    __syncthreads();
    for (int i = tid; i < NP; i += 1024)
        if (g_rowcnt[i] > 0) atomicOr(&s_mb[i >> 5], 1u << (i & 31));
    __syncthreads();

    bool conflictEver = false;   // uniform across threads (read after barriers)
    int  lastAcc = 0;            // number of +100000 adds materialized in g_priorCost

    for (int iter = 0; iter < 4096; iter++) {
        if (tid == 0) { s_nA = 0; s_nFb = 0; s_newc = 0; }
        __syncthreads();
        for (int gg = tid; gg < NG; gg += 1024)
            if (g_colcnt[gg] == 0) { int u = atomicAdd(&s_nA, 1); s_list[u] = (short)gg; }
        __syncthreads();
        int nA = s_nA;
        if (nA == 0) break;

        // eager single-add accumulation + argmin (only after latch fired)
        if (conflictEver) {
            for (int p = wid; p < P; p += 32) {
                float* row = g_priorCost + (size_t)p * NG;
                float bv = 3.4e38f; int bj = 0x7fffffff;
                for (int jj = lane; jj < NG; jj += 32) {
                    float v = row[jj] + 100000.0f;
                    row[jj] = v;
                    if (v < bv || (v == bv && jj < bj)) { bv = v; bj = jj; }
                }
                #pragma unroll
                for (int off = 16; off; off >>= 1) {
                    float ov = __shfl_down_sync(0xffffffffu, bv, off);
                    int   oj = __shfl_down_sync(0xffffffffu, bj, off);
                    if (ov < bv || (ov == bv && oj < bj)) { bv = ov; bj = oj; }
                }
                if (lane == 0) s_pbj[p] = (short)bj;
            }
            lastAcc = iter + 1;
        }

        // candidate walk: first unmatched among the 5 globally smallest
        for (int u = tid; u < nA; u += 1024) {
            int gg = s_list[u];
            int chosen = -1;
            #pragma unroll
            for (int q = 0; q < 5; q++) {
                int r = g_cand[gg * 5 + q];
                if (chosen < 0 && !((s_mb[r >> 5] >> (r & 31)) & 1u)) chosen = r;
            }
            if (chosen < 0) { int f = atomicAdd(&s_nFb, 1); s_fb[f] = (short)u; }
            s_sel[u] = (short)chosen;
        }
        __syncthreads();

        // fallback: full column scan over unmatched rows
        int nFb = s_nFb;
        for (int f = wid; f < nFb; f += 32) {
            int u = s_fb[f]; int gg = s_list[u];
            const float* col = g_cost + (size_t)gg * NP;
            float bv = 3.4e38f; int bi = 0x7fffffff;
            for (int i = lane; i < NP; i += 32) {
                if (!((s_mb[i >> 5] >> (i & 31)) & 1u)) {
                    float v = col[i];
                    if (v < bv || (v == bv && i < bi)) { bv = v; bi = i; }
                }
            }
            #pragma unroll
            for (int off = 16; off; off >>= 1) {
                float ov = __shfl_down_sync(0xffffffffu, bv, off);
                int   oi = __shfl_down_sync(0xffffffffu, bi, off);
                if (ov < bv || (ov == bv && oi < bi)) { bv = ov; bi = oi; }
            }
            if (lane == 0) s_sel[u] = (short)bi;
        }
        __syncthreads();

        // apply
        for (int u = tid; u < nA; u += 1024) {
            int r = (int)s_sel[u];
            if (r < 0) continue;
            int gg = s_list[u];
            atomicMin(&g_minGt[r], gg);
            int old = atomicAdd(&g_rowcnt[r], 1);
            if (old >= 1) atomicAdd(&s_newc, 1);
            g_colcnt[gg] = 1;
        }
        __syncthreads();
        for (int u = tid; u < nA; u += 1024) {
            int r = (int)s_sel[u];
            if (r >= 0) atomicOr(&s_mb[r >> 5], 1u << (r & 31));
        }
        __syncthreads();

        // first conflict: catch up exactly (iter+1 - lastAcc sequential adds)
        if (!conflictEver && s_newc > 0) {
            int adds = iter + 1 - lastAcc;
            for (int p = wid; p < P; p += 32) {
                float* row = g_priorCost + (size_t)p * NG;
                float bv = 3.4e38f; int bj = 0x7fffffff;
                for (int jj = lane; jj < NG; jj += 32) {
                    float v = row[jj];
                    #pragma unroll 1
                    for (int t = 0; t < adds; t++) v += 100000.0f;
                    row[jj] = v;
                    if (v < bv || (v == bv && jj < bj)) { bv = v; bj = jj; }
                }
                #pragma unroll
                for (int off = 16; off; off >>= 1) {
                    float ov = __shfl_down_sync(0xffffffffu, bv, off);
                    int   oj = __shfl_down_sync(0xffffffffu, bj, off);
                    if (ov < bv || (ov == bv && oj < bj)) { bv = ov; bj = oj; }
                }
                if (lane == 0) s_pbj[p] = (short)bj;
            }
            lastAcc = iter + 1;
            conflictEver = true;
            __syncthreads();
        } else if (s_newc > 0) {
            // latch already set; nothing extra
        }
        if (!conflictEver) { __syncthreads(); continue; }

        // m_fix for prior rows (latched, like reference's persistent any())
        for (int p = tid; p < P; p += 1024) {
            int bj = (int)s_pbj[p];
            int cur = g_priorCur[p];
            if (bj != cur) {
                atomicSub(&g_colcnt[cur], 1);
                atomicAdd(&g_colcnt[bj], 1);
                g_priorCur[p] = bj;
            }
        }
        __syncthreads();
    }

    // outputs
    for (int i = tid; i < NP; i += 1024) {
        int fg = g_rowcnt[i] > 0;
        out[i] = fg ? 1.0f : 0.0f;
        int mg = 0;
        if (fg) { int m = g_minGt[i]; if (m != 0x7fffffff) mg = m; }
        out[NP + i] = (float)mg;
    }
    __syncthreads();
    for (int p = tid; p < P; p += 1024)
        out[NP + g_priorList[p]] = (float)g_priorCur[p];
}

extern "C" void kernel_launch(void* const* d_in, const int* in_sizes, int n_in,
                              void* d_out, int out_size) {
    const float* logits = (const float*)d_in[0];
    const float* pb     = (const float*)d_in[1];
    const float* gb     = (const float*)d_in[2];
    const int*   labels = (const int*)  d_in[3];
    const int*   p_h    = (const int*)  d_in[4];
    const int*   p_w    = (const int*)  d_in[5];

    init_kernel<<<(NP + 255) / 256, 256>>>();
    prep_kernel<<<(NP + 255) / 256, 256>>>(logits, pb, gb, p_h, p_w);
    pair_kernel<<<NG, 256>>>(pb, gb, labels, p_h, p_w);
    fix_kernel<<<(NP + 255) / 256, 256>>>();
    gather_kernel<<<PMAX, 256>>>();
    loop_kernel<<<1, 1024>>>((float*)d_out);
}

// round 12
// speedup vs baseline: 3.4234x; 1.2275x over previous
#include <cuda_runtime.h>
#include <math.h>

#define NP 10000
#define NG 1000
#define NC 80
#define PMAX 2500

// ---- persistent device scratch ----
__device__ float  g_cost[(size_t)NG * NP];   // column-major: [j][i]
__device__ float  g_cls [(size_t)NC * NP];   // transposed cls cost table
__device__ float4 g_pn  [NP];
__device__ float  g_vadd[NP];
__device__ int    g_rowcnt[NP];
__device__ int    g_minGt [NP];
__device__ int    g_priorFlag[NP];
__device__ int    g_colcnt[NG];
__device__ int    g_cand[NG * 5];
__device__ int    g_dk[NG];
__device__ int    g_priorCount;
__device__ int    g_priorList[PMAX];
__device__ int    g_priorCur [PMAX];
__device__ float  g_priorCost[(size_t)PMAX * NG];

__device__ __forceinline__ float cls_cost_f(float x) {
    float p   = (x >= 0.f) ? (1.f / (1.f + expf(-x))) : (expf(x) / (1.f + expf(x)));
    float omp = 1.f - p;
    float pos = -logf(p + 1e-12f) * 0.25f * (omp * omp);
    float neg = -log1pf(-(p - 1e-12f)) * 0.75f * (p * p);
    return (pos - neg) * 2.0f;
}

__device__ __forceinline__ bool cost_less(float av, int ai, float bv, int bi) {
    return (av < bv) || (av == bv && ai < bi);
}

__global__ void init_kernel() {
    int t = blockIdx.x * blockDim.x + threadIdx.x;
    if (t < NP) { g_rowcnt[t] = 0; g_priorFlag[t] = 0; g_minGt[t] = 0x7fffffff; }
    if (t < NG) g_colcnt[t] = 0;
    if (t == 0) g_priorCount = 0;
}

// thread per (pred, class-quad): full-chip transcendental throughput.
__global__ void cls_kernel(const float* __restrict__ logits) {
    int i  = blockIdx.x * blockDim.x + threadIdx.x;
    int cq = blockIdx.y;                       // 0..19, 4 classes each
    if (i >= NP) return;
    float4 v = *reinterpret_cast<const float4*>(logits + (size_t)i * NC + cq * 4);
    g_cls[(size_t)(cq * 4 + 0) * NP + i] = cls_cost_f(v.x);
    g_cls[(size_t)(cq * 4 + 1) * NP + i] = cls_cost_f(v.y);
    g_cls[(size_t)(cq * 4 + 2) * NP + i] = cls_cost_f(v.z);
    g_cls[(size_t)(cq * 4 + 3) * NP + i] = cls_cost_f(v.w);
}

// warp per pred: ballot-parallel validity scan (early exit) + normalized box.
__global__ void valid_kernel(const float* __restrict__ pb, const float* __restrict__ gb,
                             const int* __restrict__ p_h, const int* __restrict__ p_w) {
    int wid  = threadIdx.x >> 5, lane = threadIdx.x & 31;
    int i = blockIdx.x * 8 + wid;
    if (i >= NP) return;
    float fw = (float)(*p_w), fh = (float)(*p_h);
    float4 p = reinterpret_cast<const float4*>(pb)[i];
    float pcx = (p.x + p.z) * 0.5f, pcy = (p.y + p.w) * 0.5f;

    int valid = 0;
    for (int jb = 0; jb < NG; jb += 32) {
        float4 g = reinterpret_cast<const float4*>(gb)[jb + lane];
        bool ib = (pcx > g.x) && (pcx < g.z) && (pcy > g.y) && (pcy < g.w);
        float gcx = (g.x + g.z) * 0.5f, gcy = (g.y + g.w) * 0.5f;
        float gw = g.z - g.x, gh = g.w - g.y;
        bool ic = (pcx > gcx - 2.5f * gw) && (pcx < gcx + 2.5f * gw) &&
                  (pcy > gcy - 2.5f * gh) && (pcy < gcy + 2.5f * gh);
        unsigned hit = __ballot_sync(0xffffffffu, ib || ic);
        if (hit) { valid = 1; break; }
    }
    if (lane == 0) {
        g_vadd[i] = valid ? 0.0f : 10000.0f;
        float4 pn;
        pn.x = p.x / fw; pn.y = p.y / fh; pn.z = p.z / fw; pn.w = p.w / fh;
        g_pn[i] = pn;
    }
}

__device__ __forceinline__ void merge_lists(float* aio, float* acv, int* aci,
                                            const float* bio, const float* bcv, const int* bci) {
    float rio[5];
    { int ia = 0, ib = 0;
      #pragma unroll
      for (int q = 0; q < 5; q++) rio[q] = (aio[ia] >= bio[ib]) ? aio[ia++] : bio[ib++];
    }
    float rcv[5]; int rci[5];
    { int ia = 0, ib = 0;
      #pragma unroll
      for (int q = 0; q < 5; q++) {
          if (cost_less(acv[ia], aci[ia], bcv[ib], bci[ib])) { rcv[q] = acv[ia]; rci[q] = aci[ia]; ia++; }
          else                                               { rcv[q] = bcv[ib]; rci[q] = bci[ib]; ib++; }
      }
    }
    #pragma unroll
    for (int q = 0; q < 5; q++) { aio[q] = rio[q]; acv[q] = rcv[q]; aci[q] = rci[q]; }
}

// FUSED: one block per gt. Cost column written once; scalar-register top-5
// ious (dynamic_k) + 5 lowest (cost,idx); initial assignments.
__global__ void __launch_bounds__(256, 4)
pair_kernel(const float* __restrict__ pb, const float* __restrict__ gb,
            const int* __restrict__ labels,
            const int* __restrict__ p_h, const int* __restrict__ p_w) {
    int j = blockIdx.x;
    __shared__ float s_io[256 * 5];
    __shared__ float s_cv[256 * 5];
    __shared__ int   s_ci[256 * 5];

    float fw = (float)(*p_w), fh = (float)(*p_h);
    float4 g = reinterpret_cast<const float4*>(gb)[j];
    int lab = labels[j];
    float gx1 = g.x, gy1 = g.y, gx2 = g.z, gy2 = g.w;
    float ag  = (gx2 - gx1) * (gy2 - gy1);
    float gcx = (gx1 + gx2) * 0.5f, gcy = (gy1 + gy2) * 0.5f;
    float gw  = gx2 - gx1, gh = gy2 - gy1;
    float n0 = gx1 / fw, n1 = gy1 / fh, n2 = gx2 / fw, n3 = gy2 / fh;
    float lo_x = gcx - 2.5f * gw, hi_x = gcx + 2.5f * gw;
    float lo_y = gcy - 2.5f * gh, hi_y = gcy + 2.5f * gh;
    const float* __restrict__ clsCol  = g_cls + (size_t)lab * NP;
    float*       __restrict__ costCol = g_cost + (size_t)j * NP;

    float i0 = -3.4e38f, i1 = -3.4e38f, i2 = -3.4e38f, i3 = -3.4e38f, i4 = -3.4e38f;
    float c0 = 3.4e38f, c1 = 3.4e38f, c2 = 3.4e38f, c3 = 3.4e38f, c4v = 3.4e38f;
    int   x0 = 0x7fffffff, x1 = 0x7fffffff, x2 = 0x7fffffff, x3 = 0x7fffffff, x4 = 0x7fffffff;

#define INS_IOU(v) do { float _v = (v);                                              \
    if (_v > i4) { i4 = _v;                                                          \
        if (i4 > i3) { float _t = i3; i3 = i4; i4 = _t;                              \
            if (i3 > i2) { _t = i2; i2 = i3; i3 = _t;                                \
                if (i2 > i1) { _t = i1; i1 = i2; i2 = _t;                            \
                    if (i1 > i0) { _t = i0; i0 = i1; i1 = _t; } } } } } } while (0)

#define INS_COST(v, idx) do { float _v = (v); int _i = (idx);                        \
    if (cost_less(_v, _i, c4v, x4)) { c4v = _v; x4 = _i;                             \
        if (cost_less(c4v, x4, c3, x3)) { float _t = c3; c3 = c4v; c4v = _t; int _u = x3; x3 = x4; x4 = _u; \
            if (cost_less(c3, x3, c2, x2)) { _t = c2; c2 = c3; c3 = _t; _u = x2; x2 = x3; x3 = _u; \
                if (cost_less(c2, x2, c1, x1)) { _t = c1; c1 = c2; c2 = _t; _u = x1; x1 = x2; x2 = _u; \
                    if (cost_less(c1, x1, c0, x0)) { _t = c0; c0 = c1; c1 = _t; _u = x0; x0 = x1; x1 = _u; } } } } } } while (0)

    for (int i = threadIdx.x; i < NP; i += 256) {
        float4 p  = reinterpret_cast<const float4*>(pb)[i];
        float4 pn = g_pn[i];
        float ap  = (p.z - p.x) * (p.w - p.y);
        float ltx = fmaxf(p.x, gx1), lty = fmaxf(p.y, gy1);
        float rbx = fminf(p.z, gx2), rby = fminf(p.w, gy2);
        float iw = fmaxf(rbx - ltx, 0.f), ih = fmaxf(rby - lty, 0.f);
        float inter = iw * ih;
        float uni = ap + ag - inter;
        float iou = inter / fmaxf(uni, 1e-12f);
        float ex = fmaxf(fmaxf(p.z, gx2) - fminf(p.x, gx1), 0.f);
        float ey = fmaxf(fmaxf(p.w, gy2) - fminf(p.y, gy1), 0.f);
        float enc = ex * ey;
        float giou = iou - (enc - uni) / fmaxf(enc, 1e-12f);
        float l1 = fabsf(pn.x - n0) + fabsf(pn.y - n1) +
                   fabsf(pn.z - n2) + fabsf(pn.w - n3);
        float cost = clsCol[i] + l1 * 5.0f + (-giou * 2.0f);
        float pcx = (p.x + p.z) * 0.5f, pcy = (p.y + p.w) * 0.5f;
        bool ib = (pcx > gx1) && (pcx < gx2) && (pcy > gy1) && (pcy < gy2);
        bool ic = (pcx > lo_x) && (pcx < hi_x) && (pcy > lo_y) && (pcy < hi_y);
        cost = cost + ((ib && ic) ? 0.0f : 100.0f);
        cost = cost + g_vadd[i];
        costCol[i] = cost;

        INS_IOU(iou);
        INS_COST(cost, i);
    }
#undef INS_IOU
#undef INS_COST

    int t = threadIdx.x;
    s_io[t*5+0]=i0; s_io[t*5+1]=i1; s_io[t*5+2]=i2; s_io[t*5+3]=i3; s_io[t*5+4]=i4;
    s_cv[t*5+0]=c0; s_cv[t*5+1]=c1; s_cv[t*5+2]=c2; s_cv[t*5+3]=c3; s_cv[t*5+4]=c4v;
    s_ci[t*5+0]=x0; s_ci[t*5+1]=x1; s_ci[t*5+2]=x2; s_ci[t*5+3]=x3; s_ci[t*5+4]=x4;
    __syncthreads();
    for (int stride = 128; stride > 0; stride >>= 1) {
        if (t < stride)
            merge_lists(&s_io[t*5], &s_cv[t*5], &s_ci[t*5],
                        &s_io[(t+stride)*5], &s_cv[(t+stride)*5], &s_ci[(t+stride)*5]);
        __syncthreads();
    }
    if (t == 0) {
        float s = 0.f;
        for (int q = 0; q < 5; q++) s += s_io[q];
        int dk = (int)s;
        if (dk < 1) dk = 1;
        if (dk > 5) dk = 5;
        g_dk[j] = dk;
        for (int q = 0; q < 5; q++) g_cand[j * 5 + q] = s_ci[q];
        for (int q = 0; q < dk; q++) {
            int r = s_ci[q];
            atomicMin(&g_minGt[r], j);
            atomicAdd(&g_rowcnt[r], 1);
        }
    }
}

// over-assigned rows: flag + append only (argmin lives in gather_kernel).
__global__ void fix_kernel() {
    int i = blockIdx.x * blockDim.x + threadIdx.x;
    if (i >= NP) return;
    if (g_rowcnt[i] > 1) {
        int p = atomicAdd(&g_priorCount, 1);
        if (p < PMAX) {
            g_priorFlag[i] = 1;
            g_priorList[p] = i;
        }
        g_rowcnt[i] = 1;
    }
}

// Gather prior rows into compact row-major scratch AND compute the row argmin.
__global__ void gather_kernel() {
    int p = blockIdx.x;
    if (p >= g_priorCount || p >= PMAX) return;
    int i = g_priorList[p];
    __shared__ float s_v[256];
    __shared__ int   s_j[256];
    float bv = 3.4e38f; int bj = 0x7fffffff;
    for (int j = threadIdx.x; j < NG; j += 256) {
        float v = g_cost[(size_t)j * NP + i];
        g_priorCost[(size_t)p * NG + j] = v;
        if (v < bv) { bv = v; bj = j; }   // ascending j per thread -> lowest j on ties
    }
    s_v[threadIdx.x] = bv; s_j[threadIdx.x] = bj;
    __syncthreads();
    for (int s = 128; s > 0; s >>= 1) {
        if (threadIdx.x < s) {
            float ov = s_v[threadIdx.x + s]; int oj = s_j[threadIdx.x + s];
            if (ov < s_v[threadIdx.x] || (ov == s_v[threadIdx.x] && oj < s_j[threadIdx.x])) {
                s_v[threadIdx.x] = ov; s_j[threadIdx.x] = oj;
            }
        }
        __syncthreads();
    }
    if (threadIdx.x == 0) g_priorCur[p] = s_j[0];
}

// Device-side while-loop + output write (single block, 1024 threads).
// Conflict latch is one-way; pre-latch prior-row accumulation is skipped and
// caught up exactly (sequential +100000.0f) when the latch fires.
__global__ void loop_kernel(float* __restrict__ out) {
    __shared__ unsigned s_mb[(NP + 31) / 32];
    __shared__ short s_list[NG], s_sel[NG], s_fb[NG];
    __shared__ short s_pbj[PMAX];
    __shared__ int s_nA, s_nFb, s_newc;
    int tid = threadIdx.x, wid = tid >> 5, lane = tid & 31;
    int P = g_priorCount;
    if (P > PMAX) P = PMAX;

    for (int j = tid; j < NG; j += 1024) {
        int dk = g_dk[j], c = 0;
        for (int q = 0; q < dk; q++) {
            int r = g_cand[j * 5 + q];
            if (!g_priorFlag[r]) c++;
        }
        g_colcnt[j] = c;
    }
    __syncthreads();
    for (int p = tid; p < P; p += 1024) atomicAdd(&g_colcnt[g_priorCur[p]], 1);

    for (int w = tid; w < (NP + 31) / 32; w += 1024) s_mb[w] = 0u;
    __syncthreads();
    for (int i = tid; i < NP; i += 1024)
        if (g_rowcnt[i] > 0) atomicOr(&s_mb[i >> 5], 1u << (i & 31));
    __syncthreads();

    bool conflictEver = false;
    int  lastAcc = 0;

    for (int iter = 0; iter < 4096; iter++) {
        if (tid == 0) { s_nA = 0; s_nFb = 0; s_newc = 0; }
        __syncthreads();
        for (int gg = tid; gg < NG; gg += 1024)
            if (g_colcnt[gg] == 0) { int u = atomicAdd(&s_nA, 1); s_list[u] = (short)gg; }
        __syncthreads();
        int nA = s_nA;
        if (nA == 0) break;

        if (conflictEver) {
            for (int p = wid; p < P; p += 32) {
                float* row = g_priorCost + (size_t)p * NG;
                float bv = 3.4e38f; int bj = 0x7fffffff;
                for (int jj = lane; jj < NG; jj += 32) {
                    float v = row[jj] + 100000.0f;
                    row[jj] = v;
                    if (v < bv || (v == bv && jj < bj)) { bv = v; bj = jj; }
                }
                #pragma unroll
                for (int off = 16; off; off >>= 1) {
                    float ov = __shfl_down_sync(0xffffffffu, bv, off);
                    int   oj = __shfl_down_sync(0xffffffffu, bj, off);
                    if (ov < bv || (ov == bv && oj < bj)) { bv = ov; bj = oj; }
                }
                if (lane == 0) s_pbj[p] = (short)bj;
            }
            lastAcc = iter + 1;
        }

        for (int u = tid; u < nA; u += 1024) {
            int gg = s_list[u];
            int chosen = -1;
            #pragma unroll
            for (int q = 0; q < 5; q++) {
                int r = g_cand[gg * 5 + q];
                if (chosen < 0 && !((s_mb[r >> 5] >> (r & 31)) & 1u)) chosen = r;
            }
            if (chosen < 0) { int f = atomicAdd(&s_nFb, 1); s_fb[f] = (short)u; }
            s_sel[u] = (short)chosen;
        }
        __syncthreads();

        int nFb = s_nFb;
        for (int f = wid; f < nFb; f += 32) {
            int u = s_fb[f]; int gg = s_list[u];
            const float* col = g_cost + (size_t)gg * NP;
            float bv = 3.4e38f; int bi = 0x7fffffff;
            for (int i = lane; i < NP; i += 32) {
                if (!((s_mb[i >> 5] >> (i & 31)) & 1u)) {
                    float v = col[i];
                    if (v < bv || (v == bv && i < bi)) { bv = v; bi = i; }
                }
            }
            #pragma unroll
            for (int off = 16; off; off >>= 1) {
                float ov = __shfl_down_sync(0xffffffffu, bv, off);
                int   oi = __shfl_down_sync(0xffffffffu, bi, off);
                if (ov < bv || (ov == bv && oi < bi)) { bv = ov; bi = oi; }
            }
            if (lane == 0) s_sel[u] = (short)bi;
        }
        __syncthreads();

        for (int u = tid; u < nA; u += 1024) {
            int r = (int)s_sel[u];
            if (r < 0) continue;
            int gg = s_list[u];
            atomicMin(&g_minGt[r], gg);
            int old = atomicAdd(&g_rowcnt[r], 1);
            if (old >= 1) atomicAdd(&s_newc, 1);
            g_colcnt[gg] = 1;
        }
        __syncthreads();
        for (int u = tid; u < nA; u += 1024) {
            int r = (int)s_sel[u];
            if (r >= 0) atomicOr(&s_mb[r >> 5], 1u << (r & 31));
        }
        __syncthreads();

        if (!conflictEver && s_newc > 0) {
            int adds = iter + 1 - lastAcc;
            for (int p = wid; p < P; p += 32) {
                float* row = g_priorCost + (size_t)p * NG;
                float bv = 3.4e38f; int bj = 0x7fffffff;
                for (int jj = lane; jj < NG; jj += 32) {
                    float v = row[jj];
                    #pragma unroll 1
                    for (int t = 0; t < adds; t++) v += 100000.0f;
                    row[jj] = v;
                    if (v < bv || (v == bv && jj < bj)) { bv = v; bj = jj; }
                }
                #pragma unroll
                for (int off = 16; off; off >>= 1) {
                    float ov = __shfl_down_sync(0xffffffffu, bv, off);
                    int   oj = __shfl_down_sync(0xffffffffu, bj, off);
                    if (ov < bv || (ov == bv && oj < bj)) { bv = ov; bj = oj; }
                }
                if (lane == 0) s_pbj[p] = (short)bj;
            }
            lastAcc = iter + 1;
            conflictEver = true;
            __syncthreads();
        }
        if (!conflictEver) { __syncthreads(); continue; }

        for (int p = tid; p < P; p += 1024) {
            int bj = (int)s_pbj[p];
            int cur = g_priorCur[p];
            if (bj != cur) {
                atomicSub(&g_colcnt[cur], 1);
                atomicAdd(&g_colcnt[bj], 1);
                g_priorCur[p] = bj;
            }
        }
        __syncthreads();
    }

    for (int i = tid; i < NP; i += 1024) {
        int fg = g_rowcnt[i] > 0;
        out[i] = fg ? 1.0f : 0.0f;
        int mg = 0;
        if (fg) { int m = g_minGt[i]; if (m != 0x7fffffff) mg = m; }
        out[NP + i] = (float)mg;
    }
    __syncthreads();
    for (int p = tid; p < P; p += 1024)
        out[NP + g_priorList[p]] = (float)g_priorCur[p];
}

extern "C" void kernel_launch(void* const* d_in, const int* in_sizes, int n_in,
                              void* d_out, int out_size) {
    const float* logits = (const float*)d_in[0];
    const float* pb     = (const float*)d_in[1];
    const float* gb     = (const float*)d_in[2];
    const int*   labels = (const int*)  d_in[3];
    const int*   p_h    = (const int*)  d_in[4];
    const int*   p_w    = (const int*)  d_in[5];

    init_kernel<<<(NP + 255) / 256, 256>>>();
    dim3 gCls((NP + 255) / 256, NC / 4 / 5 * 5 / 4);  // (40, 20)
    cls_kernel<<<dim3((NP + 255) / 256, NC / 4), 256>>>(logits);
    valid_kernel<<<(NP + 7) / 8, 256>>>(pb, gb, p_h, p_w);
    pair_kernel<<<NG, 256>>>(pb, gb, labels, p_h, p_w);
    fix_kernel<<<(NP + 255) / 256, 256>>>();
    gather_kernel<<<PMAX, 256>>>();
    loop_kernel<<<1, 1024>>>((float*)d_out);
}